// round 1
// baseline (speedup 1.0000x reference)
#include <cuda_runtime.h>
#include <math.h>
#include <stddef.h>

// ---------------- problem constants ----------------
constexpr int BB   = 8;
constexpr int TT   = 16;
constexpr int NN   = 256;
constexpr int CB   = 1024;
constexpr int HH   = 16;
constexpr int HDD  = 64;
constexpr int KEXP = 8;
constexpr int BTT  = BB * TT;          // 128
constexpr int MROWS = BTT * NN;        // 32768
constexpr float EPS = 1e-5f;

// ---------------- device scratch (allocation-free rule: __device__ globals) ----------------
__device__ __align__(128) float g_qsum[KEXP * CB];
__device__ __align__(128) float g_ksum[KEXP * CB];
__device__ __align__(128) float g_dyn[BB * NN * KEXP];
__device__ __align__(128) float g_qscale[BB * NN * CB];
__device__ __align__(128) float g_kscale[BB * NN * CB];
__device__ __align__(128) float g_v  [(size_t)MROWS * CB];
__device__ __align__(128) float g_qp [(size_t)MROWS * CB];
__device__ __align__(128) float g_kp [(size_t)MROWS * CB];
__device__ __align__(128) float g_vp [(size_t)MROWS * CB];
__device__ __align__(128) float g_ctx[(size_t)MROWS * CB];
__device__ __align__(128) float g_attn[(size_t)BTT * HH * NN * NN];   // 537 MB

// ---------------- expert sums: qsum[k,c] = sum_r q_experts[k,r,c] ----------------
__global__ void expert_sum_kernel(const float* __restrict__ qe, const float* __restrict__ ke) {
    int c = blockIdx.x * 256 + threadIdx.x;
    int k = blockIdx.y;
    const float* src = blockIdx.z ? ke : qe;
    float* dst = blockIdx.z ? g_ksum : g_qsum;
    const float* p = src + (size_t)k * CB * CB + c;
    float s = 0.f;
    #pragma unroll 4
    for (int r = 0; r < CB; r++) s += p[(size_t)r * CB];
    dst[k * CB + c] = s;
}

// ---------------- dyn = softmax(y @ dyn_w^T + dyn_b): one warp per (b,n) row ----------------
__global__ void dyn_kernel(const float* __restrict__ y, const float* __restrict__ dw,
                           const float* __restrict__ db) {
    int row  = blockIdx.x * 8 + (threadIdx.x >> 5);
    int lane = threadIdx.x & 31;
    const float* yr = y + (size_t)row * CB;
    float acc[KEXP];
    #pragma unroll
    for (int j = 0; j < KEXP; j++) acc[j] = 0.f;
    for (int c = lane * 4; c < CB; c += 128) {
        float4 yv = *(const float4*)(yr + c);
        #pragma unroll
        for (int j = 0; j < KEXP; j++) {
            float4 w = *(const float4*)(dw + j * CB + c);
            acc[j] += yv.x * w.x + yv.y * w.y + yv.z * w.z + yv.w * w.w;
        }
    }
    #pragma unroll
    for (int j = 0; j < KEXP; j++)
        #pragma unroll
        for (int off = 16; off > 0; off >>= 1)
            acc[j] += __shfl_xor_sync(0xffffffffu, acc[j], off);
    if (lane == 0) {
        float l[KEXP], m = -1e30f;
        #pragma unroll
        for (int j = 0; j < KEXP; j++) { l[j] = acc[j] + db[j]; m = fmaxf(m, l[j]); }
        float s = 0.f;
        #pragma unroll
        for (int j = 0; j < KEXP; j++) { l[j] = expf(l[j] - m); s += l[j]; }
        float inv = 1.f / s;
        #pragma unroll
        for (int j = 0; j < KEXP; j++) g_dyn[row * KEXP + j] = l[j] * inv;
    }
}

// ---------------- q_scale/k_scale[bn,c] = sum_k dyn[bn,k] * {q,k}sum[k,c] ----------------
__global__ void scale_kernel() {
    int c  = blockIdx.x * 256 + threadIdx.x;
    int bn = blockIdx.y;
    const float* d = g_dyn + bn * KEXP;
    float qs = 0.f, ks = 0.f;
    #pragma unroll
    for (int j = 0; j < KEXP; j++) {
        float dj = d[j];
        qs += dj * g_qsum[j * CB + c];
        ks += dj * g_ksum[j * CB + c];
    }
    g_qscale[(size_t)bn * CB + c] = qs;
    g_kscale[(size_t)bn * CB + c] = ks;
}

// ---------------- generic fp32 tiled GEMM ----------------
// C[m,n] = alpha * sum_k Aeff[m,k] * B'[k,n] (+ bias[n]) (+ resid[m,n])
//   BTRANS=true : B' = W^T with W an (Ndim x Kdim) row-major weight (ldb over k)
//   SCALEA      : Aeff[m,k] = A[m,k] * scaleA[srow(m)*C + k],  srow(m) = (m/4096)*256 + m%256
//   BMODE 0: no batch; 1: QK^T scores batch; 2: attn@V ctx batch
template<int BM, int BN, int BK, int TM, int TN, bool BTRANS, bool SCALEA, int BMODE>
__global__ void __launch_bounds__((BM / TM) * (BN / TN))
gemm_k(const float* __restrict__ A, const float* __restrict__ B, float* __restrict__ Cm,
       int Kdim, int lda, int ldb, int ldc,
       const float* __restrict__ bias, const float* __restrict__ scaleA,
       const float* __restrict__ resid, float alpha)
{
    constexpr int NT   = (BM / TM) * (BN / TN);
    constexpr int AREG = BM * BK / (4 * NT);
    constexpr int BREG = BN * BK / (4 * NT);
    static_assert(TN == 8, "epilogue assumes TN==8");
    const int tid = threadIdx.x;

    if (BMODE == 1) {
        int z = blockIdx.z;
        size_t head = (size_t)(z >> 4) * NN * CB + (size_t)(z & 15) * HDD;
        A += head; B += head; Cm += (size_t)z * NN * NN;
    } else if (BMODE == 2) {
        int z = blockIdx.z;
        size_t head = (size_t)(z >> 4) * NN * CB + (size_t)(z & 15) * HDD;
        A += (size_t)z * NN * NN; B += head; Cm += head;
    }
    const int bm = blockIdx.y * BM, bn = blockIdx.x * BN;

    __shared__ float As[BK][BM];
    __shared__ float Bs[BK][BN];
    float4 aR[AREG], bR[BREG];

    auto loadA = [&](int kt) {
        #pragma unroll
        for (int r = 0; r < AREG; r++) {
            int i = tid + r * NT;
            int row = i / (BK / 4), c4 = (i % (BK / 4)) * 4;
            float4 v = *(const float4*)(A + (size_t)(bm + row) * lda + kt + c4);
            if (SCALEA) {
                int gr = bm + row;
                int srow = ((gr >> 12) << 8) | (gr & 255);
                float4 s = *(const float4*)(scaleA + (size_t)srow * CB + kt + c4);
                v.x *= s.x; v.y *= s.y; v.z *= s.z; v.w *= s.w;
            }
            aR[r] = v;
        }
    };
    auto storeA = [&]() {
        #pragma unroll
        for (int r = 0; r < AREG; r++) {
            int i = tid + r * NT;
            int row = i / (BK / 4), c4 = (i % (BK / 4)) * 4;
            As[c4 + 0][row] = aR[r].x; As[c4 + 1][row] = aR[r].y;
            As[c4 + 2][row] = aR[r].z; As[c4 + 3][row] = aR[r].w;
        }
    };
    auto loadB = [&](int kt) {
        #pragma unroll
        for (int r = 0; r < BREG; r++) {
            int i = tid + r * NT;
            if (BTRANS) {
                int row = i / (BK / 4), c4 = (i % (BK / 4)) * 4;
                bR[r] = *(const float4*)(B + (size_t)(bn + row) * ldb + kt + c4);
            } else {
                int row = i / (BN / 4), c4 = (i % (BN / 4)) * 4;
                bR[r] = *(const float4*)(B + (size_t)(kt + row) * ldb + bn + c4);
            }
        }
    };
    auto storeB = [&]() {
        #pragma unroll
        for (int r = 0; r < BREG; r++) {
            int i = tid + r * NT;
            if (BTRANS) {
                int row = i / (BK / 4), c4 = (i % (BK / 4)) * 4;
                Bs[c4 + 0][row] = bR[r].x; Bs[c4 + 1][row] = bR[r].y;
                Bs[c4 + 2][row] = bR[r].z; Bs[c4 + 3][row] = bR[r].w;
            } else {
                int row = i / (BN / 4), c4 = (i % (BN / 4)) * 4;
                *(float4*)(&Bs[row][c4]) = bR[r];
            }
        }
    };

    float acc[TM][TN];
    #pragma unroll
    for (int i = 0; i < TM; i++)
        #pragma unroll
        for (int j = 0; j < TN; j++) acc[i][j] = 0.f;

    loadA(0); loadB(0); storeA(); storeB();
    __syncthreads();

    const int ntiles = Kdim / BK;
    const int ty = tid / (BN / TN), tx = tid % (BN / TN);

    for (int t = 0; t < ntiles; t++) {
        if (t + 1 < ntiles) { loadA((t + 1) * BK); loadB((t + 1) * BK); }
        #pragma unroll
        for (int kk = 0; kk < BK; kk++) {
            float a[TM], b[TN];
            #pragma unroll
            for (int i = 0; i < TM; i++) a[i] = As[kk][ty * TM + i];
            #pragma unroll
            for (int j = 0; j < TN; j++) b[j] = Bs[kk][tx * TN + j];
            #pragma unroll
            for (int i = 0; i < TM; i++)
                #pragma unroll
                for (int j = 0; j < TN; j++) acc[i][j] += a[i] * b[j];
        }
        __syncthreads();
        if (t + 1 < ntiles) { storeA(); storeB(); __syncthreads(); }
    }

    // epilogue
    const int col0 = bn + tx * TN;
    float4 bv0 = {0,0,0,0}, bv1 = {0,0,0,0};
    if (bias) { bv0 = *(const float4*)(bias + col0); bv1 = *(const float4*)(bias + col0 + 4); }
    #pragma unroll
    for (int i = 0; i < TM; i++) {
        int row = bm + ty * TM + i;
        float4 o0, o1;
        o0.x = acc[i][0] * alpha + bv0.x; o0.y = acc[i][1] * alpha + bv0.y;
        o0.z = acc[i][2] * alpha + bv0.z; o0.w = acc[i][3] * alpha + bv0.w;
        o1.x = acc[i][4] * alpha + bv1.x; o1.y = acc[i][5] * alpha + bv1.y;
        o1.z = acc[i][6] * alpha + bv1.z; o1.w = acc[i][7] * alpha + bv1.w;
        if (resid) {
            float4 r0 = *(const float4*)(resid + (size_t)row * ldc + col0);
            float4 r1 = *(const float4*)(resid + (size_t)row * ldc + col0 + 4);
            o0.x += r0.x; o0.y += r0.y; o0.z += r0.z; o0.w += r0.w;
            o1.x += r1.x; o1.y += r1.y; o1.z += r1.z; o1.w += r1.w;
        }
        *(float4*)(Cm + (size_t)row * ldc + col0)     = o0;
        *(float4*)(Cm + (size_t)row * ldc + col0 + 4) = o1;
    }
}

// ---------------- softmax over last dim (256) of g_attn; one warp per row ----------------
__global__ void softmax_kernel(float* __restrict__ S) {
    int row  = blockIdx.x * 8 + (threadIdx.x >> 5);
    int lane = threadIdx.x & 31;
    float* p = S + (size_t)row * NN + lane * 8;
    float4 a = ((float4*)p)[0];
    float4 b = ((float4*)p)[1];
    float m = fmaxf(fmaxf(fmaxf(a.x, a.y), fmaxf(a.z, a.w)),
                    fmaxf(fmaxf(b.x, b.y), fmaxf(b.z, b.w)));
    #pragma unroll
    for (int off = 16; off > 0; off >>= 1) m = fmaxf(m, __shfl_xor_sync(0xffffffffu, m, off));
    a.x = __expf(a.x - m); a.y = __expf(a.y - m); a.z = __expf(a.z - m); a.w = __expf(a.w - m);
    b.x = __expf(b.x - m); b.y = __expf(b.y - m); b.z = __expf(b.z - m); b.w = __expf(b.w - m);
    float s = a.x + a.y + a.z + a.w + b.x + b.y + b.z + b.w;
    #pragma unroll
    for (int off = 16; off > 0; off >>= 1) s += __shfl_xor_sync(0xffffffffu, s, off);
    float inv = 1.f / s;
    a.x *= inv; a.y *= inv; a.z *= inv; a.w *= inv;
    b.x *= inv; b.y *= inv; b.z *= inv; b.w *= inv;
    ((float4*)p)[0] = a;
    ((float4*)p)[1] = b;
}

// ---------------- attn_avg = mean over heads ----------------
__global__ void attn_avg_kernel(const float* __restrict__ attn, float* __restrict__ out2) {
    size_t idx = (size_t)blockIdx.x * 256 + threadIdx.x;     // < BT*N*N
    size_t bt  = idx >> 16;                                   // N*N = 65536
    size_t rem = idx & 65535;
    const float* p = attn + bt * ((size_t)HH * NN * NN) + rem;
    float s = 0.f;
    #pragma unroll
    for (int h = 0; h < HH; h++) s += p[(size_t)h * NN * NN];
    out2[idx] = s * (1.f / HH);
}

// ---------------- in-place LayerNorm, one block per row of 1024 ----------------
__device__ __forceinline__ float block_sum(float v) {
    __shared__ float sh[8];
    int lane = threadIdx.x & 31, w = threadIdx.x >> 5;
    #pragma unroll
    for (int off = 16; off > 0; off >>= 1) v += __shfl_xor_sync(0xffffffffu, v, off);
    if (lane == 0) sh[w] = v;
    __syncthreads();
    float t = (threadIdx.x < 8) ? sh[threadIdx.x] : 0.f;
    if (w == 0) {
        #pragma unroll
        for (int off = 4; off > 0; off >>= 1) t += __shfl_xor_sync(0xffffffffu, t, off);
        if (lane == 0) sh[0] = t;
    }
    __syncthreads();
    float r = sh[0];
    __syncthreads();
    return r;
}

__global__ void ln_kernel(float* __restrict__ h, const float* __restrict__ gamma,
                          const float* __restrict__ beta) {
    int row = blockIdx.x;
    float* p = h + (size_t)row * CB;
    float4 v = ((float4*)p)[threadIdx.x];
    float mu = block_sum(v.x + v.y + v.z + v.w) * (1.f / CB);
    float d0 = v.x - mu, d1 = v.y - mu, d2 = v.z - mu, d3 = v.w - mu;
    float var = block_sum(d0 * d0 + d1 * d1 + d2 * d2 + d3 * d3) * (1.f / CB);
    float inv = rsqrtf(var + EPS);
    float4 g  = ((const float4*)gamma)[threadIdx.x];
    float4 be = ((const float4*)beta)[threadIdx.x];
    float4 o;
    o.x = d0 * inv * g.x + be.x;
    o.y = d1 * inv * g.y + be.y;
    o.z = d2 * inv * g.z + be.z;
    o.w = d3 * inv * g.w + be.w;
    ((float4*)p)[threadIdx.x] = o;
}

// ---------------- launch ----------------
extern "C" void kernel_launch(void* const* d_in, const int* in_sizes, int n_in,
                              void* d_out, int out_size) {
    const float* x    = (const float*)d_in[0];
    const float* y    = (const float*)d_in[1];
    /* d_in[2] = mask — constant all-true in this problem; unused */
    const float* q_ex = (const float*)d_in[3];
    const float* k_ex = (const float*)d_in[4];
    const float* dynw = (const float*)d_in[5];
    const float* dynb = (const float*)d_in[6];
    const float* v_w  = (const float*)d_in[7];
    const float* v_b  = (const float*)d_in[8];
    const float* in_w = (const float*)d_in[9];
    const float* in_b = (const float*)d_in[10];
    const float* o_w  = (const float*)d_in[11];
    const float* o_b  = (const float*)d_in[12];
    const float* gam  = (const float*)d_in[13];
    const float* bet  = (const float*)d_in[14];

    float* out1 = (float*)d_out;                         // (BT*N, C) layernorm output
    float* out2 = out1 + (size_t)MROWS * CB;             // (BT, N, N) attn_avg

    float *p_qscale, *p_kscale, *p_v, *p_qp, *p_kp, *p_vp, *p_attn, *p_ctx;
    cudaGetSymbolAddress((void**)&p_qscale, g_qscale);
    cudaGetSymbolAddress((void**)&p_kscale, g_kscale);
    cudaGetSymbolAddress((void**)&p_v,      g_v);
    cudaGetSymbolAddress((void**)&p_qp,     g_qp);
    cudaGetSymbolAddress((void**)&p_kp,     g_kp);
    cudaGetSymbolAddress((void**)&p_vp,     g_vp);
    cudaGetSymbolAddress((void**)&p_attn,   g_attn);
    cudaGetSymbolAddress((void**)&p_ctx,    g_ctx);

    // 1) expert column sums
    expert_sum_kernel<<<dim3(CB / 256, KEXP, 2), 256>>>(q_ex, k_ex);
    // 2) dyn softmax
    dyn_kernel<<<(BB * NN) / 8, 256>>>(y, dynw, dynb);
    // 3) q/k scales
    scale_kernel<<<dim3(CB / 256, BB * NN), 256>>>();

    // 4) v = x @ v_w^T + v_b
    gemm_k<128,128,16,8,8,true,false,0><<<dim3(8, 256, 1), 256>>>(
        x, v_w, p_v, CB, CB, CB, CB, v_b, nullptr, nullptr, 1.f);
    // 5) qp = (x * q_scale) @ wq^T + bq
    gemm_k<128,128,16,8,8,true,true,0><<<dim3(8, 256, 1), 256>>>(
        x, in_w, p_qp, CB, CB, CB, CB, in_b, p_qscale, nullptr, 1.f);
    // 6) kp = (x * k_scale) @ wk^T + bk
    gemm_k<128,128,16,8,8,true,true,0><<<dim3(8, 256, 1), 256>>>(
        x, in_w + (size_t)CB * CB, p_kp, CB, CB, CB, CB, in_b + CB, p_kscale, nullptr, 1.f);
    // 7) vp = v @ wv^T + bv
    gemm_k<128,128,16,8,8,true,false,0><<<dim3(8, 256, 1), 256>>>(
        p_v, in_w + (size_t)2 * CB * CB, p_vp, CB, CB, CB, CB, in_b + 2 * CB, nullptr, nullptr, 1.f);

    // 8) scores = qp_h @ kp_h^T / sqrt(HD), batched over BT*H
    gemm_k<128,128,16,8,8,true,false,1><<<dim3(2, 2, BTT * HH), 256>>>(
        p_qp, p_kp, p_attn, HDD, CB, CB, NN, nullptr, nullptr, nullptr, 0.125f);
    // 9) softmax rows
    softmax_kernel<<<(BTT * HH * NN) / 8, 256>>>(p_attn);
    // 10) attn_avg -> output region 2
    attn_avg_kernel<<<(BTT * NN * NN) / 256, 256>>>(p_attn, out2);
    // 11) ctx = attn @ vp_h, batched
    gemm_k<128,64,16,8,8,false,false,2><<<dim3(1, 2, BTT * HH), 128>>>(
        p_attn, p_vp, p_ctx, NN, NN, CB, CB, nullptr, nullptr, nullptr, 1.f);

    // 12) h = x + ctx @ out_w^T + out_b  -> out1
    gemm_k<128,128,16,8,8,true,false,0><<<dim3(8, 256, 1), 256>>>(
        p_ctx, o_w, out1, CB, CB, CB, CB, o_b, nullptr, x, 1.f);
    // 13) LayerNorm in-place on out1
    ln_kernel<<<MROWS, 256>>>(out1, gam, bet);
}

// round 4
// speedup vs baseline: 1.4297x; 1.4297x over previous
#include <cuda_runtime.h>
#include <cuda_bf16.h>
#include <math.h>
#include <stddef.h>
#include <stdint.h>

// ---------------- problem constants ----------------
constexpr int BB   = 8;
constexpr int TT   = 16;
constexpr int NN   = 256;
constexpr int CB   = 1024;
constexpr int HH   = 16;
constexpr int HDD  = 64;
constexpr int KEXP = 8;
constexpr int BTT  = BB * TT;          // 128
constexpr int MROWS = BTT * NN;        // 32768
constexpr float EPS = 1e-5f;

// ---------------- device scratch ----------------
__device__ __align__(128) float g_qsum[KEXP * CB];
__device__ __align__(128) float g_ksum[KEXP * CB];
__device__ __align__(128) float g_dyn[BB * NN * KEXP];
__device__ __align__(128) float g_qscale[BB * NN * CB];
__device__ __align__(128) float g_kscale[BB * NN * CB];
__device__ __align__(128) float g_v  [(size_t)MROWS * CB];
__device__ __align__(128) float g_qp [(size_t)MROWS * CB];
__device__ __align__(128) float g_kp [(size_t)MROWS * CB];
__device__ __align__(128) float g_vp [(size_t)MROWS * CB];
__device__ __align__(128) float g_ctx[(size_t)MROWS * CB];
__device__ __align__(128) float g_attn[(size_t)BTT * HH * NN * NN];   // 537 MB

// ---------------- helpers ----------------
__device__ __forceinline__ uint32_t smem_u32(const void* p) {
    return (uint32_t)__cvta_generic_to_shared(p);
}
// XOR swizzle for 128B rows: chunk(16B) ^= (row & 7)
__device__ __forceinline__ uint32_t sw128(uint32_t o) { return o ^ ((o >> 3) & 0x70); }
__device__ __forceinline__ uint32_t pack2(float a, float b) {
    __nv_bfloat162 t = __floats2bfloat162_rn(a, b);
    return *(uint32_t*)&t;
}
__device__ __forceinline__ void ldsm_x4(uint32_t& r0, uint32_t& r1, uint32_t& r2, uint32_t& r3,
                                        uint32_t addr) {
    asm volatile("ldmatrix.sync.aligned.m8n8.x4.shared.b16 {%0,%1,%2,%3}, [%4];"
                 : "=r"(r0), "=r"(r1), "=r"(r2), "=r"(r3) : "r"(addr));
}
__device__ __forceinline__ void mma16816(float* d, const uint32_t* a, uint32_t b0, uint32_t b1) {
    asm volatile("mma.sync.aligned.m16n8k16.row.col.f32.bf16.bf16.f32 "
                 "{%0,%1,%2,%3}, {%4,%5,%6,%7}, {%8,%9}, {%0,%1,%2,%3};"
                 : "+f"(d[0]), "+f"(d[1]), "+f"(d[2]), "+f"(d[3])
                 : "r"(a[0]), "r"(a[1]), "r"(a[2]), "r"(a[3]), "r"(b0), "r"(b1));
}

// ---------------- split-bf16 HMMA GEMM ----------------
// C[M,N] = alpha * Aeff @ B^T (+bias) (+resid)
// NS splits/operand, NP product pairs. BK=64, BM=128, 256 threads (8 warps, 4x2).
// BMODE 0: plain NT (B = weights [N,K], k contig)
// BMODE 1: per-head scores (A=qp,B=kp head slices; C=attn[z])
// BMODE 2: PV (A=attn[z], B=vp head slice [K,N] n-contig -> transposed fill; C=ctx head)
template<int BN, int NS, int NP, bool SCALEA, int BMODE>
__global__ void __launch_bounds__(256, 1)
hmma_gemm(const float* __restrict__ A, const float* __restrict__ B, float* __restrict__ Cm,
          int Kdim, int lda, int ldb, int ldc,
          const float* __restrict__ bias, const float* __restrict__ scaleA,
          const float* __restrict__ resid, float alpha)
{
    constexpr int ATILE  = 128 * 64 * 2;          // 16 KB bf16
    constexpr int BTILE  = BN * 64 * 2;
    constexpr int STAGE  = NS * (ATILE + BTILE);
    constexpr int AREG   = 8;                     // 128*16 float4 / 256
    constexpr int BREG   = (BMODE == 2) ? 4 : (BN * 16 / 256);
    constexpr int NTILES = (BN / 2) / 8;          // n-tiles (8 cols) per warp

    extern __shared__ char dsm[];
    const uint32_t sraw  = smem_u32(dsm);
    const uint32_t sbase = (sraw + 127u) & ~127u;
    char* const ab       = dsm + (sbase - sraw);

    const int tid  = threadIdx.x;
    const int wid  = tid >> 5;
    const int lane = tid & 31;
    const int wm   = wid & 3;          // 4 warps along M
    const int wn   = wid >> 2;         // 2 warps along N

    if (BMODE == 1) {
        int z = blockIdx.z;
        size_t off = (size_t)(z >> 4) * NN * CB + (size_t)(z & 15) * HDD;
        A += off; B += off; Cm += (size_t)z * NN * NN;
    } else if (BMODE == 2) {
        int z = blockIdx.z;
        size_t off = (size_t)(z >> 4) * NN * CB + (size_t)(z & 15) * HDD;
        A += (size_t)z * NN * NN; B += off; Cm += off;
    }
    const int bm = blockIdx.y * 128, bn = blockIdx.x * BN;

    float4 aR[AREG], bR[BREG];

    auto ldgA = [&](int kt) {
        #pragma unroll
        for (int r = 0; r < AREG; r++) {
            int i = tid + r * 256;
            int row = i >> 4, c4 = (i & 15) * 4;
            float4 v = *(const float4*)(A + (size_t)(bm + row) * lda + kt + c4);
            if (SCALEA) {
                int gr = bm + row;
                int srow = ((gr >> 12) << 8) | (gr & 255);
                float4 s = *(const float4*)(scaleA + (size_t)srow * CB + kt + c4);
                v.x *= s.x; v.y *= s.y; v.z *= s.z; v.w *= s.w;
            }
            aR[r] = v;
        }
    };
    auto ldgB = [&](int kt) {
        if (BMODE == 2) {
            // B gmem [k][n] (n contig); read along n
            #pragma unroll
            for (int r = 0; r < BREG; r++) {
                int i = tid + r * 256;
                int k = i >> 4, n4 = (i & 15) * 4;
                bR[r] = *(const float4*)(B + (size_t)(kt + k) * ldb + n4);
            }
        } else {
            #pragma unroll
            for (int r = 0; r < BREG; r++) {
                int i = tid + r * 256;
                int row = i >> 4, c4 = (i & 15) * 4;
                bR[r] = *(const float4*)(B + (size_t)(bn + row) * ldb + kt + c4);
            }
        }
    };

    auto fill = [&](int s) {
        char* st = ab + s * STAGE;
        // A splits
        #pragma unroll
        for (int r = 0; r < AREG; r++) {
            int i = tid + r * 256;
            int row = i >> 4, c4 = (i & 15) * 4;
            uint32_t off = sw128((uint32_t)(row * 128 + c4 * 2));
            float in[4] = {aR[r].x, aR[r].y, aR[r].z, aR[r].w};
            float hi[4], md[4], lo[4];
            #pragma unroll
            for (int j = 0; j < 4; j++) {
                float a = in[j];
                float h = __bfloat162float(__float2bfloat16(a));
                hi[j] = h;
                float rr = a - h;
                if (NS == 3) {
                    float m = __bfloat162float(__float2bfloat16(rr));
                    md[j] = m; lo[j] = rr - m;
                } else { md[j] = rr; lo[j] = 0.f; }
            }
            *(uint2*)(st + off)         = make_uint2(pack2(hi[0], hi[1]), pack2(hi[2], hi[3]));
            *(uint2*)(st + ATILE + off) = make_uint2(pack2(md[0], md[1]), pack2(md[2], md[3]));
            if (NS == 3)
                *(uint2*)(st + 2 * ATILE + off) = make_uint2(pack2(lo[0], lo[1]), pack2(lo[2], lo[3]));
        }
        // B splits
        char* bt = st + NS * ATILE;
        if (BMODE == 2) {
            #pragma unroll
            for (int r = 0; r < BREG; r++) {
                int i = tid + r * 256;
                int k = i >> 4, n4 = (i & 15) * 4;
                float in[4] = {bR[r].x, bR[r].y, bR[r].z, bR[r].w};
                #pragma unroll
                for (int j = 0; j < 4; j++) {
                    float a = in[j];
                    float h = __bfloat162float(__float2bfloat16(a));
                    float rr = a - h;
                    uint32_t off = sw128((uint32_t)((n4 + j) * 128 + k * 2));
                    *(__nv_bfloat16*)(bt + off)         = __float2bfloat16(h);
                    *(__nv_bfloat16*)(bt + BTILE + off) = __float2bfloat16(rr);
                }
            }
        } else {
            #pragma unroll
            for (int r = 0; r < BREG; r++) {
                int i = tid + r * 256;
                int row = i >> 4, c4 = (i & 15) * 4;
                uint32_t off = sw128((uint32_t)(row * 128 + c4 * 2));
                float in[4] = {bR[r].x, bR[r].y, bR[r].z, bR[r].w};
                float hi[4], md[4], lo[4];
                #pragma unroll
                for (int j = 0; j < 4; j++) {
                    float a = in[j];
                    float h = __bfloat162float(__float2bfloat16(a));
                    hi[j] = h;
                    float rr = a - h;
                    if (NS == 3) {
                        float m = __bfloat162float(__float2bfloat16(rr));
                        md[j] = m; lo[j] = rr - m;
                    } else { md[j] = rr; lo[j] = 0.f; }
                }
                *(uint2*)(bt + off)         = make_uint2(pack2(hi[0], hi[1]), pack2(hi[2], hi[3]));
                *(uint2*)(bt + BTILE + off) = make_uint2(pack2(md[0], md[1]), pack2(md[2], md[3]));
                if (NS == 3)
                    *(uint2*)(bt + 2 * BTILE + off) = make_uint2(pack2(lo[0], lo[1]), pack2(lo[2], lo[3]));
            }
        }
    };

    float acc[2][NTILES][4];
    #pragma unroll
    for (int mt = 0; mt < 2; mt++)
        #pragma unroll
        for (int nt = 0; nt < NTILES; nt++)
            #pragma unroll
            for (int j = 0; j < 4; j++) acc[mt][nt][j] = 0.f;

    // per-lane ldmatrix offsets (within tile)
    const uint32_t a_roff = (uint32_t)((wm * 32 + (lane & 15)) * 128 + ((lane >> 4) << 4));
    const uint32_t b_roff = (uint32_t)((wn * (BN / 2) + ((lane >> 4) << 3) + (lane & 7)) * 128
                                       + (((lane >> 3) & 1) << 4));

    const int PA3[3] = {0, 0, 1},          PB3[3] = {0, 1, 0};
    const int PA6[6] = {0, 0, 1, 0, 2, 1}, PB6[6] = {0, 1, 0, 2, 0, 1};

    auto compute = [&](int s) {
        uint32_t st = sbase + s * STAGE;
        #pragma unroll
        for (int p = 0; p < NP; p++) {
            int pa = (NP == 6) ? PA6[p] : PA3[p];
            int pb = (NP == 6) ? PB6[p] : PB3[p];
            uint32_t abp = st + pa * ATILE;
            uint32_t bbp = st + NS * ATILE + pb * BTILE;
            #pragma unroll
            for (int ks = 0; ks < 4; ks++) {
                uint32_t a[2][4];
                #pragma unroll
                for (int mt = 0; mt < 2; mt++)
                    ldsm_x4(a[mt][0], a[mt][1], a[mt][2], a[mt][3],
                            abp + sw128(a_roff + mt * 16 * 128 + ks * 32));
                #pragma unroll
                for (int bp = 0; bp < NTILES / 2; bp++) {
                    uint32_t b0, b1, b2, b3;
                    ldsm_x4(b0, b1, b2, b3, bbp + sw128(b_roff + bp * 16 * 128 + ks * 32));
                    #pragma unroll
                    for (int mt = 0; mt < 2; mt++) {
                        mma16816(acc[mt][2 * bp],     a[mt], b0, b1);
                        mma16816(acc[mt][2 * bp + 1], a[mt], b2, b3);
                    }
                }
            }
        }
    };

    const int nch = Kdim / 64;
    ldgA(0); ldgB(0); fill(0);
    __syncthreads();
    for (int t = 0; t < nch; t++) {
        if (t + 1 < nch) { ldgA((t + 1) * 64); ldgB((t + 1) * 64); }
        compute(t & 1);
        __syncthreads();
        if (t + 1 < nch) {
            fill((t + 1) & 1);
            __syncthreads();
        }
    }

    // ---- epilogue ----
    #pragma unroll
    for (int mt = 0; mt < 2; mt++) {
        int r0 = bm + wm * 32 + mt * 16 + (lane >> 2);
        #pragma unroll
        for (int nt = 0; nt < NTILES; nt++) {
            int col = bn + wn * (BN / 2) + nt * 8 + (lane & 3) * 2;
            #pragma unroll
            for (int rr = 0; rr < 2; rr++) {
                int row = r0 + rr * 8;
                float v0 = acc[mt][nt][2 * rr]     * alpha;
                float v1 = acc[mt][nt][2 * rr + 1] * alpha;
                if (bias)  { v0 += bias[col]; v1 += bias[col + 1]; }
                if (resid) {
                    const float* rp = resid + (size_t)row * ldc + col;
                    v0 += rp[0]; v1 += rp[1];
                }
                float2 o = {v0, v1};
                *(float2*)(Cm + (size_t)row * ldc + col) = o;
            }
        }
    }
}

// ---------------- expert sums ----------------
__global__ void expert_sum_kernel(const float* __restrict__ qe, const float* __restrict__ ke) {
    int c = blockIdx.x * 256 + threadIdx.x;
    int k = blockIdx.y;
    const float* src = blockIdx.z ? ke : qe;
    float* dst = blockIdx.z ? g_ksum : g_qsum;
    const float* p = src + (size_t)k * CB * CB + c;
    float s = 0.f;
    #pragma unroll 4
    for (int r = 0; r < CB; r++) s += p[(size_t)r * CB];
    dst[k * CB + c] = s;
}

// ---------------- dyn softmax ----------------
__global__ void dyn_kernel(const float* __restrict__ y, const float* __restrict__ dw,
                           const float* __restrict__ db) {
    int row  = blockIdx.x * 8 + (threadIdx.x >> 5);
    int lane = threadIdx.x & 31;
    const float* yr = y + (size_t)row * CB;
    float acc[KEXP];
    #pragma unroll
    for (int j = 0; j < KEXP; j++) acc[j] = 0.f;
    for (int c = lane * 4; c < CB; c += 128) {
        float4 yv = *(const float4*)(yr + c);
        #pragma unroll
        for (int j = 0; j < KEXP; j++) {
            float4 w = *(const float4*)(dw + j * CB + c);
            acc[j] += yv.x * w.x + yv.y * w.y + yv.z * w.z + yv.w * w.w;
        }
    }
    #pragma unroll
    for (int j = 0; j < KEXP; j++)
        #pragma unroll
        for (int off = 16; off > 0; off >>= 1)
            acc[j] += __shfl_xor_sync(0xffffffffu, acc[j], off);
    if (lane == 0) {
        float l[KEXP], m = -1e30f;
        #pragma unroll
        for (int j = 0; j < KEXP; j++) { l[j] = acc[j] + db[j]; m = fmaxf(m, l[j]); }
        float s = 0.f;
        #pragma unroll
        for (int j = 0; j < KEXP; j++) { l[j] = expf(l[j] - m); s += l[j]; }
        float inv = 1.f / s;
        #pragma unroll
        for (int j = 0; j < KEXP; j++) g_dyn[row * KEXP + j] = l[j] * inv;
    }
}

// ---------------- q/k scales ----------------
__global__ void scale_kernel() {
    int c  = blockIdx.x * 256 + threadIdx.x;
    int bn = blockIdx.y;
    const float* d = g_dyn + bn * KEXP;
    float qs = 0.f, ks = 0.f;
    #pragma unroll
    for (int j = 0; j < KEXP; j++) {
        float dj = d[j];
        qs += dj * g_qsum[j * CB + c];
        ks += dj * g_ksum[j * CB + c];
    }
    g_qscale[(size_t)bn * CB + c] = qs;
    g_kscale[(size_t)bn * CB + c] = ks;
}

// ---------------- softmax over last dim ----------------
__global__ void softmax_kernel(float* __restrict__ S) {
    int row  = blockIdx.x * 8 + (threadIdx.x >> 5);
    int lane = threadIdx.x & 31;
    float* p = S + (size_t)row * NN + lane * 8;
    float4 a = ((float4*)p)[0];
    float4 b = ((float4*)p)[1];
    float m = fmaxf(fmaxf(fmaxf(a.x, a.y), fmaxf(a.z, a.w)),
                    fmaxf(fmaxf(b.x, b.y), fmaxf(b.z, b.w)));
    #pragma unroll
    for (int off = 16; off > 0; off >>= 1) m = fmaxf(m, __shfl_xor_sync(0xffffffffu, m, off));
    a.x = __expf(a.x - m); a.y = __expf(a.y - m); a.z = __expf(a.z - m); a.w = __expf(a.w - m);
    b.x = __expf(b.x - m); b.y = __expf(b.y - m); b.z = __expf(b.z - m); b.w = __expf(b.w - m);
    float s = a.x + a.y + a.z + a.w + b.x + b.y + b.z + b.w;
    #pragma unroll
    for (int off = 16; off > 0; off >>= 1) s += __shfl_xor_sync(0xffffffffu, s, off);
    float inv = 1.f / s;
    a.x *= inv; a.y *= inv; a.z *= inv; a.w *= inv;
    b.x *= inv; b.y *= inv; b.z *= inv; b.w *= inv;
    ((float4*)p)[0] = a;
    ((float4*)p)[1] = b;
}

// ---------------- attn_avg ----------------
__global__ void attn_avg_kernel(const float* __restrict__ attn, float* __restrict__ out2) {
    size_t idx = (size_t)blockIdx.x * 256 + threadIdx.x;
    size_t bt  = idx >> 16;
    size_t rem = idx & 65535;
    const float* p = attn + bt * ((size_t)HH * NN * NN) + rem;
    float s = 0.f;
    #pragma unroll
    for (int h = 0; h < HH; h++) s += p[(size_t)h * NN * NN];
    out2[idx] = s * (1.f / HH);
}

// ---------------- LayerNorm ----------------
__device__ __forceinline__ float block_sum(float v) {
    __shared__ float sh[8];
    int lane = threadIdx.x & 31, w = threadIdx.x >> 5;
    #pragma unroll
    for (int off = 16; off > 0; off >>= 1) v += __shfl_xor_sync(0xffffffffu, v, off);
    if (lane == 0) sh[w] = v;
    __syncthreads();
    float t = (threadIdx.x < 8) ? sh[threadIdx.x] : 0.f;
    if (w == 0) {
        #pragma unroll
        for (int off = 4; off > 0; off >>= 1) t += __shfl_xor_sync(0xffffffffu, t, off);
        if (lane == 0) sh[0] = t;
    }
    __syncthreads();
    float r = sh[0];
    __syncthreads();
    return r;
}

__global__ void ln_kernel(float* __restrict__ h, const float* __restrict__ gamma,
                          const float* __restrict__ beta) {
    int row = blockIdx.x;
    float* p = h + (size_t)row * CB;
    float4 v = ((float4*)p)[threadIdx.x];
    float mu = block_sum(v.x + v.y + v.z + v.w) * (1.f / CB);
    float d0 = v.x - mu, d1 = v.y - mu, d2 = v.z - mu, d3 = v.w - mu;
    float var = block_sum(d0 * d0 + d1 * d1 + d2 * d2 + d3 * d3) * (1.f / CB);
    float inv = rsqrtf(var + EPS);
    float4 g  = ((const float4*)gamma)[threadIdx.x];
    float4 be = ((const float4*)beta)[threadIdx.x];
    float4 o;
    o.x = d0 * inv * g.x + be.x;
    o.y = d1 * inv * g.y + be.y;
    o.z = d2 * inv * g.z + be.z;
    o.w = d3 * inv * g.w + be.w;
    ((float4*)p)[threadIdx.x] = o;
}

// ---------------- launch ----------------
extern "C" void kernel_launch(void* const* d_in, const int* in_sizes, int n_in,
                              void* d_out, int out_size) {
    const float* x    = (const float*)d_in[0];
    const float* y    = (const float*)d_in[1];
    const float* q_ex = (const float*)d_in[3];
    const float* k_ex = (const float*)d_in[4];
    const float* dynw = (const float*)d_in[5];
    const float* dynb = (const float*)d_in[6];
    const float* v_w  = (const float*)d_in[7];
    const float* v_b  = (const float*)d_in[8];
    const float* in_w = (const float*)d_in[9];
    const float* in_b = (const float*)d_in[10];
    const float* o_w  = (const float*)d_in[11];
    const float* o_b  = (const float*)d_in[12];
    const float* gam  = (const float*)d_in[13];
    const float* bet  = (const float*)d_in[14];

    float* out1 = (float*)d_out;
    float* out2 = out1 + (size_t)MROWS * CB;

    float *p_qscale, *p_kscale, *p_v, *p_qp, *p_kp, *p_vp, *p_attn, *p_ctx;
    cudaGetSymbolAddress((void**)&p_qscale, g_qscale);
    cudaGetSymbolAddress((void**)&p_kscale, g_kscale);
    cudaGetSymbolAddress((void**)&p_v,      g_v);
    cudaGetSymbolAddress((void**)&p_qp,     g_qp);
    cudaGetSymbolAddress((void**)&p_kp,     g_kp);
    cudaGetSymbolAddress((void**)&p_vp,     g_vp);
    cudaGetSymbolAddress((void**)&p_attn,   g_attn);
    cudaGetSymbolAddress((void**)&p_ctx,    g_ctx);

    // smem: 128 align slack + 2 stages
    const int SM_NP6 = 256 + 2 * 3 * (16384 + 16384);   // 196864  (qp/kp/scores)
    const int SM_NP3 = 256 + 2 * 2 * (16384 + 16384);   // 131328  (v/vp/out)
    const int SM_PV  = 256 + 2 * 2 * (16384 + 8192);    //  98560  (PV)
    cudaFuncSetAttribute(hmma_gemm<128,2,3,false,0>, cudaFuncAttributeMaxDynamicSharedMemorySize, SM_NP3);
    cudaFuncSetAttribute(hmma_gemm<128,3,6,true ,0>, cudaFuncAttributeMaxDynamicSharedMemorySize, SM_NP6);
    cudaFuncSetAttribute(hmma_gemm<128,3,6,false,1>, cudaFuncAttributeMaxDynamicSharedMemorySize, SM_NP6);
    cudaFuncSetAttribute(hmma_gemm<64 ,2,3,false,2>, cudaFuncAttributeMaxDynamicSharedMemorySize, SM_PV);

    // 1-3) prep
    expert_sum_kernel<<<dim3(CB / 256, KEXP, 2), 256>>>(q_ex, k_ex);
    dyn_kernel<<<(BB * NN) / 8, 256>>>(y, dynw, dynb);
    scale_kernel<<<dim3(CB / 256, BB * NN), 256>>>();

    // 4) v = x @ v_w^T + v_b
    hmma_gemm<128,2,3,false,0><<<dim3(8, 256), 256, SM_NP3>>>(
        x, v_w, p_v, CB, CB, CB, CB, v_b, nullptr, nullptr, 1.f);
    // 5) qp = (x*q_scale) @ wq^T + bq
    hmma_gemm<128,3,6,true,0><<<dim3(8, 256), 256, SM_NP6>>>(
        x, in_w, p_qp, CB, CB, CB, CB, in_b, p_qscale, nullptr, 1.f);
    // 6) kp = (x*k_scale) @ wk^T + bk
    hmma_gemm<128,3,6,true,0><<<dim3(8, 256), 256, SM_NP6>>>(
        x, in_w + (size_t)CB * CB, p_kp, CB, CB, CB, CB, in_b + CB, p_kscale, nullptr, 1.f);
    // 7) vp = v @ wv^T + bv
    hmma_gemm<128,2,3,false,0><<<dim3(8, 256), 256, SM_NP3>>>(
        p_v, in_w + (size_t)2 * CB * CB, p_vp, CB, CB, CB, CB, in_b + 2 * CB, nullptr, nullptr, 1.f);

    // 8) scores = qp_h @ kp_h^T / 8 (batched per head)
    hmma_gemm<128,3,6,false,1><<<dim3(2, 2, BTT * HH), 256, SM_NP6>>>(
        p_qp, p_kp, p_attn, HDD, CB, CB, NN, nullptr, nullptr, nullptr, 0.125f);
    // 9) softmax
    softmax_kernel<<<(BTT * HH * NN) / 8, 256>>>(p_attn);
    // 10) attn_avg
    attn_avg_kernel<<<(BTT * NN * NN) / 256, 256>>>(p_attn, out2);
    // 11) ctx = attn @ vp_h (batched per head)
    hmma_gemm<64,2,3,false,2><<<dim3(1, 2, BTT * HH), 256, SM_PV>>>(
        p_attn, p_vp, p_ctx, NN, NN, CB, CB, nullptr, nullptr, nullptr, 1.f);

    // 12) h = x + ctx @ out_w^T + out_b
    hmma_gemm<128,2,3,false,0><<<dim3(8, 256), 256, SM_NP3>>>(
        p_ctx, o_w, out1, CB, CB, CB, CB, o_b, nullptr, x, 1.f);
    // 13) LayerNorm in-place
    ln_kernel<<<MROWS, 256>>>(out1, gam, bet);
}

// round 5
// speedup vs baseline: 1.9939x; 1.3946x over previous
#include <cuda_runtime.h>
#include <cuda_bf16.h>
#include <math.h>
#include <stddef.h>
#include <stdint.h>

// ---------------- problem constants ----------------
constexpr int BB   = 8;
constexpr int TT   = 16;
constexpr int NN   = 256;
constexpr int CB   = 1024;
constexpr int HH   = 16;
constexpr int HDD  = 64;
constexpr int KEXP = 8;
constexpr int BTT  = BB * TT;          // 128
constexpr int MROWS = BTT * NN;        // 32768
constexpr float EPS = 1e-5f;

// ---------------- device scratch ----------------
__device__ __align__(128) float g_qsum[KEXP * CB];
__device__ __align__(128) float g_ksum[KEXP * CB];
__device__ __align__(128) float g_dyn[BB * NN * KEXP];
__device__ __align__(128) float g_qscale[BB * NN * CB];
__device__ __align__(128) float g_kscale[BB * NN * CB];
__device__ __align__(128) float g_vp  [(size_t)MROWS * CB];
__device__ __align__(128) float g_attn[(size_t)BTT * HH * NN * NN];   // 537 MB

#define DECL_BF(name) __device__ __align__(128) __nv_bfloat16 name[(size_t)MROWS * CB];
DECL_BF(g_xh)  DECL_BF(g_xl)
DECL_BF(g_qh)  DECL_BF(g_qm)  DECL_BF(g_ql)
DECL_BF(g_kh)  DECL_BF(g_km)  DECL_BF(g_kl)
DECL_BF(g_vh)  DECL_BF(g_vl)
DECL_BF(g_qph) DECL_BF(g_qpm) DECL_BF(g_qpl)
DECL_BF(g_kph) DECL_BF(g_kpm) DECL_BF(g_kpl)
DECL_BF(g_cxh) DECL_BF(g_cxl)

#define DECL_W(name) __device__ __align__(128) __nv_bfloat16 name[(size_t)CB * CB];
DECL_W(w_vwh) DECL_W(w_vwl)
DECL_W(w_qh)  DECL_W(w_qm)  DECL_W(w_ql)
DECL_W(w_kh)  DECL_W(w_km)  DECL_W(w_kl)
DECL_W(w_wvh) DECL_W(w_wvl)
DECL_W(w_owh) DECL_W(w_owl)

// ---------------- helpers ----------------
__device__ __forceinline__ uint32_t smem_u32(const void* p) {
    return (uint32_t)__cvta_generic_to_shared(p);
}
__device__ __forceinline__ uint32_t sw128(uint32_t o) { return o ^ ((o >> 3) & 0x70); }
__device__ __forceinline__ uint32_t pack2(float a, float b) {
    __nv_bfloat162 t = __floats2bfloat162_rn(a, b);
    return *(uint32_t*)&t;
}
__device__ __forceinline__ float bfr(float a) {
    return __bfloat162float(__float2bfloat16(a));
}
__device__ __forceinline__ void ldsm_x4(uint32_t& r0, uint32_t& r1, uint32_t& r2, uint32_t& r3,
                                        uint32_t addr) {
    asm volatile("ldmatrix.sync.aligned.m8n8.x4.shared.b16 {%0,%1,%2,%3}, [%4];"
                 : "=r"(r0), "=r"(r1), "=r"(r2), "=r"(r3) : "r"(addr));
}
__device__ __forceinline__ void mma16816(float* d, const uint32_t* a, uint32_t b0, uint32_t b1) {
    asm volatile("mma.sync.aligned.m16n8k16.row.col.f32.bf16.bf16.f32 "
                 "{%0,%1,%2,%3}, {%4,%5,%6,%7}, {%8,%9}, {%0,%1,%2,%3};"
                 : "+f"(d[0]), "+f"(d[1]), "+f"(d[2]), "+f"(d[3])
                 : "r"(a[0]), "r"(a[1]), "r"(a[2]), "r"(a[3]), "r"(b0), "r"(b1));
}
__device__ __forceinline__ void cp16(uint32_t dst, const void* src) {
    asm volatile("cp.async.cg.shared.global [%0], [%1], 16;" :: "r"(dst), "l"(src) : "memory");
}
__device__ __forceinline__ void cp_commit() { asm volatile("cp.async.commit_group;" ::: "memory"); }
template<int N> __device__ __forceinline__ void cp_wait() {
    asm volatile("cp.async.wait_group %0;" :: "n"(N) : "memory");
}

// ---------------- async split-bf16 HMMA GEMM (pre-split operands) ----------------
// C = alpha * A @ B^T (+bias) (+resid); A,B given as NS bf16 split arrays, K-contig rows.
// Output: Cf (fp32, optional) and/or split outputs Ch/Cmid/Cl (bf16, optional).
// BMODE 0: plain. BMODE 1: per-head scores batch over blockIdx.z (head slices of A,B).
template<int NS, int NP, int BMODE>
__global__ void __launch_bounds__(256)
hmma_as(const __nv_bfloat16* __restrict__ A0, const __nv_bfloat16* __restrict__ A1,
        const __nv_bfloat16* __restrict__ A2,
        const __nv_bfloat16* __restrict__ B0, const __nv_bfloat16* __restrict__ B1,
        const __nv_bfloat16* __restrict__ B2,
        float* __restrict__ Cf, __nv_bfloat16* __restrict__ Ch,
        __nv_bfloat16* __restrict__ Cmid, __nv_bfloat16* __restrict__ Cl,
        int Kdim, int lda, int ldb, int ldc,
        const float* __restrict__ bias, const float* __restrict__ resid, float alpha)
{
    constexpr int TILE  = 128 * 64 * 2;   // 16 KB bf16 tile (128 rows x 64 k)
    constexpr int STAGE = NS * 2 * TILE;

    extern __shared__ char dsm[];
    const uint32_t sraw  = smem_u32(dsm);
    const uint32_t sbase = (sraw + 127u) & ~127u;

    const int tid  = threadIdx.x;
    const int wid  = tid >> 5;
    const int lane = tid & 31;
    const int wm   = wid & 3;
    const int wn   = wid >> 2;

    const __nv_bfloat16* Ap[3] = {A0, A1, A2};
    const __nv_bfloat16* Bp[3] = {B0, B1, B2};

    size_t aoff = 0, boff = 0;
    if (BMODE == 1) {
        int z = blockIdx.z;
        size_t off = (size_t)(z >> 4) * NN * CB + (size_t)(z & 15) * HDD;
        aoff = off; boff = off;
        Cf += (size_t)z * NN * NN;
    }
    const int bm = blockIdx.y * 128, bn = blockIdx.x * 128;

    auto issue = [&](int s, int kt) {
        uint32_t st = sbase + s * STAGE;
        #pragma unroll
        for (int p = 0; p < NS; p++) {
            const __nv_bfloat16* As = Ap[p];
            #pragma unroll
            for (int r = 0; r < 4; r++) {
                int i = tid + r * 256;
                int row = i >> 3, ch = (i & 7) * 16;
                cp16(st + p * TILE + sw128((uint32_t)(row * 128 + ch)),
                     (const char*)(As + aoff + (size_t)(bm + row) * lda + kt) + ch);
            }
        }
        #pragma unroll
        for (int p = 0; p < NS; p++) {
            const __nv_bfloat16* Bs = Bp[p];
            #pragma unroll
            for (int r = 0; r < 4; r++) {
                int i = tid + r * 256;
                int row = i >> 3, ch = (i & 7) * 16;
                cp16(st + (NS + p) * TILE + sw128((uint32_t)(row * 128 + ch)),
                     (const char*)(Bs + boff + (size_t)(bn + row) * ldb + kt) + ch);
            }
        }
        cp_commit();
    };

    float acc[2][8][4];
    #pragma unroll
    for (int mt = 0; mt < 2; mt++)
        #pragma unroll
        for (int nt = 0; nt < 8; nt++)
            #pragma unroll
            for (int j = 0; j < 4; j++) acc[mt][nt][j] = 0.f;

    const uint32_t a_roff = (uint32_t)((wm * 32 + (lane & 15)) * 128 + ((lane >> 4) << 4));
    const uint32_t b_roff = (uint32_t)((wn * 64 + ((lane >> 4) << 3) + (lane & 7)) * 128
                                       + (((lane >> 3) & 1) << 4));

    const int PA3[3] = {0, 0, 1},          PB3[3] = {0, 1, 0};
    const int PA6[6] = {0, 0, 1, 0, 2, 1}, PB6[6] = {0, 1, 0, 2, 0, 1};

    auto compute = [&](int s) {
        uint32_t st = sbase + s * STAGE;
        #pragma unroll
        for (int p = 0; p < NP; p++) {
            int pa = (NP == 6) ? PA6[p] : PA3[p];
            int pb = (NP == 6) ? PB6[p] : PB3[p];
            uint32_t abp = st + pa * TILE;
            uint32_t bbp = st + (NS + pb) * TILE;
            #pragma unroll
            for (int ks = 0; ks < 4; ks++) {
                uint32_t a[2][4];
                #pragma unroll
                for (int mt = 0; mt < 2; mt++)
                    ldsm_x4(a[mt][0], a[mt][1], a[mt][2], a[mt][3],
                            abp + sw128(a_roff + mt * 16 * 128 + ks * 32));
                #pragma unroll
                for (int bp = 0; bp < 4; bp++) {
                    uint32_t b0, b1, b2, b3;
                    ldsm_x4(b0, b1, b2, b3, bbp + sw128(b_roff + bp * 16 * 128 + ks * 32));
                    #pragma unroll
                    for (int mt = 0; mt < 2; mt++) {
                        mma16816(acc[mt][2 * bp],     a[mt], b0, b1);
                        mma16816(acc[mt][2 * bp + 1], a[mt], b2, b3);
                    }
                }
            }
        }
    };

    const int nch = Kdim / 64;
    issue(0, 0);
    if (nch > 1) issue(1, 64);
    for (int t = 0; t < nch; t++) {
        if (t + 1 < nch) cp_wait<1>(); else cp_wait<0>();
        __syncthreads();
        compute(t & 1);
        __syncthreads();
        if (t + 2 < nch) issue(t & 1, (t + 2) * 64);
    }

    // ---- epilogue ----
    #pragma unroll
    for (int mt = 0; mt < 2; mt++) {
        int r0 = bm + wm * 32 + mt * 16 + (lane >> 2);
        #pragma unroll
        for (int nt = 0; nt < 8; nt++) {
            int col = bn + wn * 64 + nt * 8 + (lane & 3) * 2;
            #pragma unroll
            for (int rr = 0; rr < 2; rr++) {
                int row = r0 + rr * 8;
                float v0 = acc[mt][nt][2 * rr]     * alpha;
                float v1 = acc[mt][nt][2 * rr + 1] * alpha;
                if (bias)  { v0 += bias[col]; v1 += bias[col + 1]; }
                if (resid) {
                    const float* rp = resid + (size_t)row * ldc + col;
                    v0 += rp[0]; v1 += rp[1];
                }
                size_t base = (size_t)row * ldc + col;
                if (Cf) *(float2*)(Cf + base) = make_float2(v0, v1);
                if (Ch) {
                    float h0 = bfr(v0), h1 = bfr(v1);
                    *(uint32_t*)(Ch + base) = pack2(h0, h1);
                    float r0f = v0 - h0, r1f = v1 - h1;
                    if (Cl) {
                        float m0 = bfr(r0f), m1 = bfr(r1f);
                        *(uint32_t*)(Cmid + base) = pack2(m0, m1);
                        *(uint32_t*)(Cl + base)   = pack2(r0f - m0, r1f - m1);
                    } else {
                        *(uint32_t*)(Cmid + base) = pack2(r0f, r1f);
                    }
                }
            }
        }
    }
}

// ---------------- PV GEMM: ctx = attn @ vp_head (register-fill, split2 output) ----------------
__global__ void __launch_bounds__(256)
pv_gemm(const float* __restrict__ A, const float* __restrict__ B,
        __nv_bfloat16* __restrict__ Ch, __nv_bfloat16* __restrict__ Cl)
{
    constexpr int BN = 64;
    constexpr int ATILE = 128 * 64 * 2;     // 16 KB
    constexpr int BTILE = BN * 64 * 2;      // 8 KB
    constexpr int STAGE = 2 * (ATILE + BTILE);

    extern __shared__ char dsm[];
    const uint32_t sraw  = smem_u32(dsm);
    const uint32_t sbase = (sraw + 127u) & ~127u;
    char* const ab       = dsm + (sbase - sraw);

    const int tid  = threadIdx.x;
    const int wid  = tid >> 5;
    const int lane = tid & 31;
    const int wm   = wid & 3;
    const int wn   = wid >> 2;

    int z = blockIdx.z;
    size_t hoff = (size_t)(z >> 4) * NN * CB + (size_t)(z & 15) * HDD;
    A += (size_t)z * NN * NN;
    B += hoff;
    const int bm = blockIdx.y * 128;

    float4 aR[8], bR[4];
    auto ldgA = [&](int kt) {
        #pragma unroll
        for (int r = 0; r < 8; r++) {
            int i = tid + r * 256;
            int row = i >> 4, c4 = (i & 15) * 4;
            aR[r] = *(const float4*)(A + (size_t)(bm + row) * NN + kt + c4);
        }
    };
    auto ldgB = [&](int kt) {
        #pragma unroll
        for (int r = 0; r < 4; r++) {
            int i = tid + r * 256;
            int k = i >> 4, n4 = (i & 15) * 4;
            bR[r] = *(const float4*)(B + (size_t)(kt + k) * CB + n4);
        }
    };
    auto fill = [&](int s) {
        char* st = ab + s * STAGE;
        #pragma unroll
        for (int r = 0; r < 8; r++) {
            int i = tid + r * 256;
            int row = i >> 4, c4 = (i & 15) * 4;
            uint32_t off = sw128((uint32_t)(row * 128 + c4 * 2));
            float in[4] = {aR[r].x, aR[r].y, aR[r].z, aR[r].w};
            float hi[4], lo[4];
            #pragma unroll
            for (int j = 0; j < 4; j++) {
                float h = bfr(in[j]); hi[j] = h; lo[j] = in[j] - h;
            }
            *(uint2*)(st + off)         = make_uint2(pack2(hi[0], hi[1]), pack2(hi[2], hi[3]));
            *(uint2*)(st + ATILE + off) = make_uint2(pack2(lo[0], lo[1]), pack2(lo[2], lo[3]));
        }
        char* bt = st + 2 * ATILE;
        #pragma unroll
        for (int r = 0; r < 4; r++) {
            int i = tid + r * 256;
            int k = i >> 4, n4 = (i & 15) * 4;
            float in[4] = {bR[r].x, bR[r].y, bR[r].z, bR[r].w};
            #pragma unroll
            for (int j = 0; j < 4; j++) {
                float h = bfr(in[j]);
                uint32_t off = sw128((uint32_t)((n4 + j) * 128 + k * 2));
                *(__nv_bfloat16*)(bt + off)         = __float2bfloat16(h);
                *(__nv_bfloat16*)(bt + BTILE + off) = __float2bfloat16(in[j] - h);
            }
        }
    };

    float acc[2][4][4];
    #pragma unroll
    for (int mt = 0; mt < 2; mt++)
        #pragma unroll
        for (int nt = 0; nt < 4; nt++)
            #pragma unroll
            for (int j = 0; j < 4; j++) acc[mt][nt][j] = 0.f;

    const uint32_t a_roff = (uint32_t)((wm * 32 + (lane & 15)) * 128 + ((lane >> 4) << 4));
    const uint32_t b_roff = (uint32_t)((wn * 32 + ((lane >> 4) << 3) + (lane & 7)) * 128
                                       + (((lane >> 3) & 1) << 4));
    const int PA3[3] = {0, 0, 1}, PB3[3] = {0, 1, 0};

    auto compute = [&](int s) {
        uint32_t st = sbase + s * STAGE;
        #pragma unroll
        for (int p = 0; p < 3; p++) {
            uint32_t abp = st + PA3[p] * ATILE;
            uint32_t bbp = st + 2 * ATILE + PB3[p] * BTILE;
            #pragma unroll
            for (int ks = 0; ks < 4; ks++) {
                uint32_t a[2][4];
                #pragma unroll
                for (int mt = 0; mt < 2; mt++)
                    ldsm_x4(a[mt][0], a[mt][1], a[mt][2], a[mt][3],
                            abp + sw128(a_roff + mt * 16 * 128 + ks * 32));
                #pragma unroll
                for (int bp = 0; bp < 2; bp++) {
                    uint32_t b0, b1, b2, b3;
                    ldsm_x4(b0, b1, b2, b3, bbp + sw128(b_roff + bp * 16 * 128 + ks * 32));
                    #pragma unroll
                    for (int mt = 0; mt < 2; mt++) {
                        mma16816(acc[mt][2 * bp],     a[mt], b0, b1);
                        mma16816(acc[mt][2 * bp + 1], a[mt], b2, b3);
                    }
                }
            }
        }
    };

    const int nch = NN / 64;   // 4
    ldgA(0); ldgB(0); fill(0);
    __syncthreads();
    for (int t = 0; t < nch; t++) {
        if (t + 1 < nch) { ldgA((t + 1) * 64); ldgB((t + 1) * 64); }
        compute(t & 1);
        __syncthreads();
        if (t + 1 < nch) {
            fill((t + 1) & 1);
            __syncthreads();
        }
    }

    // epilogue: split2 writes to ctx arrays
    #pragma unroll
    for (int mt = 0; mt < 2; mt++) {
        int r0 = bm + wm * 32 + mt * 16 + (lane >> 2);
        #pragma unroll
        for (int nt = 0; nt < 4; nt++) {
            int col = wn * 32 + nt * 8 + (lane & 3) * 2;
            #pragma unroll
            for (int rr = 0; rr < 2; rr++) {
                int row = r0 + rr * 8;
                float v0 = acc[mt][nt][2 * rr];
                float v1 = acc[mt][nt][2 * rr + 1];
                size_t base = hoff + (size_t)row * CB + col;
                float h0 = bfr(v0), h1 = bfr(v1);
                *(uint32_t*)(Ch + base) = pack2(h0, h1);
                *(uint32_t*)(Cl + base) = pack2(v0 - h0, v1 - h1);
            }
        }
    }
}

// ---------------- weight split ----------------
__global__ void wsplit_kernel(const float* __restrict__ w, __nv_bfloat16* __restrict__ h,
                              __nv_bfloat16* __restrict__ m, __nv_bfloat16* __restrict__ l,
                              int n, int ns) {
    int i = blockIdx.x * 256 + threadIdx.x;
    if (i >= n) return;
    float a  = w[i];
    float hh = bfr(a);
    h[i] = __float2bfloat16(hh);
    float r = a - hh;
    if (ns == 3) {
        float mm = bfr(r);
        m[i] = __float2bfloat16(mm);
        l[i] = __float2bfloat16(r - mm);
    } else {
        m[i] = __float2bfloat16(r);
    }
}

// ---------------- x/q/k split (q = x*qscale 3-split, k = x*kscale 3-split, x 2-split) ----------------
__global__ void qk_split_kernel(const float* __restrict__ x) {
    size_t idx = (size_t)blockIdx.x * 256 + threadIdx.x;   // over MROWS*CB/4
    size_t row = idx >> 8;
    int c4 = (int)(idx & 255) * 4;
    int srow = (int)(((row >> 12) << 8) | (row & 255));
    float4 xv = *(const float4*)(x + row * CB + c4);
    float4 qs = *(const float4*)(g_qscale + (size_t)srow * CB + c4);
    float4 ks = *(const float4*)(g_kscale + (size_t)srow * CB + c4);
    size_t base = row * CB + c4;

    float xi[4] = {xv.x, xv.y, xv.z, xv.w};
    float qi[4] = {xv.x * qs.x, xv.y * qs.y, xv.z * qs.z, xv.w * qs.w};
    float ki[4] = {xv.x * ks.x, xv.y * ks.y, xv.z * ks.z, xv.w * ks.w};

    float xh[4], xl[4];
    #pragma unroll
    for (int j = 0; j < 4; j++) { float h = bfr(xi[j]); xh[j] = h; xl[j] = xi[j] - h; }
    *(uint2*)(g_xh + base) = make_uint2(pack2(xh[0], xh[1]), pack2(xh[2], xh[3]));
    *(uint2*)(g_xl + base) = make_uint2(pack2(xl[0], xl[1]), pack2(xl[2], xl[3]));

    float qh[4], qm[4], ql[4];
    #pragma unroll
    for (int j = 0; j < 4; j++) {
        float h = bfr(qi[j]); qh[j] = h;
        float r = qi[j] - h;
        float m = bfr(r); qm[j] = m; ql[j] = r - m;
    }
    *(uint2*)(g_qh + base) = make_uint2(pack2(qh[0], qh[1]), pack2(qh[2], qh[3]));
    *(uint2*)(g_qm + base) = make_uint2(pack2(qm[0], qm[1]), pack2(qm[2], qm[3]));
    *(uint2*)(g_ql + base) = make_uint2(pack2(ql[0], ql[1]), pack2(ql[2], ql[3]));

    float kh[4], km[4], kl[4];
    #pragma unroll
    for (int j = 0; j < 4; j++) {
        float h = bfr(ki[j]); kh[j] = h;
        float r = ki[j] - h;
        float m = bfr(r); km[j] = m; kl[j] = r - m;
    }
    *(uint2*)(g_kh + base) = make_uint2(pack2(kh[0], kh[1]), pack2(kh[2], kh[3]));
    *(uint2*)(g_km + base) = make_uint2(pack2(km[0], km[1]), pack2(km[2], km[3]));
    *(uint2*)(g_kl + base) = make_uint2(pack2(kl[0], kl[1]), pack2(kl[2], kl[3]));
}

// ---------------- expert sums ----------------
__global__ void expert_sum_kernel(const float* __restrict__ qe, const float* __restrict__ ke) {
    int c = blockIdx.x * 256 + threadIdx.x;
    int k = blockIdx.y;
    const float* src = blockIdx.z ? ke : qe;
    float* dst = blockIdx.z ? g_ksum : g_qsum;
    const float* p = src + (size_t)k * CB * CB + c;
    float s = 0.f;
    #pragma unroll 4
    for (int r = 0; r < CB; r++) s += p[(size_t)r * CB];
    dst[k * CB + c] = s;
}

// ---------------- dyn softmax ----------------
__global__ void dyn_kernel(const float* __restrict__ y, const float* __restrict__ dw,
                           const float* __restrict__ db) {
    int row  = blockIdx.x * 8 + (threadIdx.x >> 5);
    int lane = threadIdx.x & 31;
    const float* yr = y + (size_t)row * CB;
    float acc[KEXP];
    #pragma unroll
    for (int j = 0; j < KEXP; j++) acc[j] = 0.f;
    for (int c = lane * 4; c < CB; c += 128) {
        float4 yv = *(const float4*)(yr + c);
        #pragma unroll
        for (int j = 0; j < KEXP; j++) {
            float4 w = *(const float4*)(dw + j * CB + c);
            acc[j] += yv.x * w.x + yv.y * w.y + yv.z * w.z + yv.w * w.w;
        }
    }
    #pragma unroll
    for (int j = 0; j < KEXP; j++)
        #pragma unroll
        for (int off = 16; off > 0; off >>= 1)
            acc[j] += __shfl_xor_sync(0xffffffffu, acc[j], off);
    if (lane == 0) {
        float l[KEXP], m = -1e30f;
        #pragma unroll
        for (int j = 0; j < KEXP; j++) { l[j] = acc[j] + db[j]; m = fmaxf(m, l[j]); }
        float s = 0.f;
        #pragma unroll
        for (int j = 0; j < KEXP; j++) { l[j] = expf(l[j] - m); s += l[j]; }
        float inv = 1.f / s;
        #pragma unroll
        for (int j = 0; j < KEXP; j++) g_dyn[row * KEXP + j] = l[j] * inv;
    }
}

// ---------------- q/k scales ----------------
__global__ void scale_kernel() {
    int c  = blockIdx.x * 256 + threadIdx.x;
    int bn = blockIdx.y;
    const float* d = g_dyn + bn * KEXP;
    float qs = 0.f, ks = 0.f;
    #pragma unroll
    for (int j = 0; j < KEXP; j++) {
        float dj = d[j];
        qs += dj * g_qsum[j * CB + c];
        ks += dj * g_ksum[j * CB + c];
    }
    g_qscale[(size_t)bn * CB + c] = qs;
    g_kscale[(size_t)bn * CB + c] = ks;
}

// ---------------- softmax ----------------
__global__ void softmax_kernel(float* __restrict__ S) {
    int row  = blockIdx.x * 8 + (threadIdx.x >> 5);
    int lane = threadIdx.x & 31;
    float* p = S + (size_t)row * NN + lane * 8;
    float4 a = ((float4*)p)[0];
    float4 b = ((float4*)p)[1];
    float m = fmaxf(fmaxf(fmaxf(a.x, a.y), fmaxf(a.z, a.w)),
                    fmaxf(fmaxf(b.x, b.y), fmaxf(b.z, b.w)));
    #pragma unroll
    for (int off = 16; off > 0; off >>= 1) m = fmaxf(m, __shfl_xor_sync(0xffffffffu, m, off));
    a.x = __expf(a.x - m); a.y = __expf(a.y - m); a.z = __expf(a.z - m); a.w = __expf(a.w - m);
    b.x = __expf(b.x - m); b.y = __expf(b.y - m); b.z = __expf(b.z - m); b.w = __expf(b.w - m);
    float s = a.x + a.y + a.z + a.w + b.x + b.y + b.z + b.w;
    #pragma unroll
    for (int off = 16; off > 0; off >>= 1) s += __shfl_xor_sync(0xffffffffu, s, off);
    float inv = 1.f / s;
    a.x *= inv; a.y *= inv; a.z *= inv; a.w *= inv;
    b.x *= inv; b.y *= inv; b.z *= inv; b.w *= inv;
    ((float4*)p)[0] = a;
    ((float4*)p)[1] = b;
}

// ---------------- attn_avg ----------------
__global__ void attn_avg_kernel(const float* __restrict__ attn, float* __restrict__ out2) {
    size_t idx = (size_t)blockIdx.x * 256 + threadIdx.x;
    size_t bt  = idx >> 16;
    size_t rem = idx & 65535;
    const float* p = attn + bt * ((size_t)HH * NN * NN) + rem;
    float s = 0.f;
    #pragma unroll
    for (int h = 0; h < HH; h++) s += p[(size_t)h * NN * NN];
    out2[idx] = s * (1.f / HH);
}

// ---------------- LayerNorm ----------------
__device__ __forceinline__ float block_sum(float v) {
    __shared__ float sh[8];
    int lane = threadIdx.x & 31, w = threadIdx.x >> 5;
    #pragma unroll
    for (int off = 16; off > 0; off >>= 1) v += __shfl_xor_sync(0xffffffffu, v, off);
    if (lane == 0) sh[w] = v;
    __syncthreads();
    float t = (threadIdx.x < 8) ? sh[threadIdx.x] : 0.f;
    if (w == 0) {
        #pragma unroll
        for (int off = 4; off > 0; off >>= 1) t += __shfl_xor_sync(0xffffffffu, t, off);
        if (lane == 0) sh[0] = t;
    }
    __syncthreads();
    float r = sh[0];
    __syncthreads();
    return r;
}

__global__ void ln_kernel(float* __restrict__ h, const float* __restrict__ gamma,
                          const float* __restrict__ beta) {
    int row = blockIdx.x;
    float* p = h + (size_t)row * CB;
    float4 v = ((float4*)p)[threadIdx.x];
    float mu = block_sum(v.x + v.y + v.z + v.w) * (1.f / CB);
    float d0 = v.x - mu, d1 = v.y - mu, d2 = v.z - mu, d3 = v.w - mu;
    float var = block_sum(d0 * d0 + d1 * d1 + d2 * d2 + d3 * d3) * (1.f / CB);
    float inv = rsqrtf(var + EPS);
    float4 g  = ((const float4*)gamma)[threadIdx.x];
    float4 be = ((const float4*)beta)[threadIdx.x];
    float4 o;
    o.x = d0 * inv * g.x + be.x;
    o.y = d1 * inv * g.y + be.y;
    o.z = d2 * inv * g.z + be.z;
    o.w = d3 * inv * g.w + be.w;
    ((float4*)p)[threadIdx.x] = o;
}

// ---------------- launch ----------------
extern "C" void kernel_launch(void* const* d_in, const int* in_sizes, int n_in,
                              void* d_out, int out_size) {
    const float* x    = (const float*)d_in[0];
    const float* y    = (const float*)d_in[1];
    const float* q_ex = (const float*)d_in[3];
    const float* k_ex = (const float*)d_in[4];
    const float* dynw = (const float*)d_in[5];
    const float* dynb = (const float*)d_in[6];
    const float* v_w  = (const float*)d_in[7];
    const float* v_b  = (const float*)d_in[8];
    const float* in_w = (const float*)d_in[9];
    const float* in_b = (const float*)d_in[10];
    const float* o_w  = (const float*)d_in[11];
    const float* o_b  = (const float*)d_in[12];
    const float* gam  = (const float*)d_in[13];
    const float* bet  = (const float*)d_in[14];

    float* out1 = (float*)d_out;
    float* out2 = out1 + (size_t)MROWS * CB;

    #define SYM(T, v, s) T* v; cudaGetSymbolAddress((void**)&v, s);
    SYM(float, p_vp, g_vp) SYM(float, p_attn, g_attn)
    SYM(__nv_bfloat16, p_xh, g_xh)  SYM(__nv_bfloat16, p_xl, g_xl)
    SYM(__nv_bfloat16, p_qh, g_qh)  SYM(__nv_bfloat16, p_qm, g_qm)  SYM(__nv_bfloat16, p_ql, g_ql)
    SYM(__nv_bfloat16, p_kh, g_kh)  SYM(__nv_bfloat16, p_km, g_km)  SYM(__nv_bfloat16, p_kl, g_kl)
    SYM(__nv_bfloat16, p_vh, g_vh)  SYM(__nv_bfloat16, p_vl, g_vl)
    SYM(__nv_bfloat16, p_qph, g_qph) SYM(__nv_bfloat16, p_qpm, g_qpm) SYM(__nv_bfloat16, p_qpl, g_qpl)
    SYM(__nv_bfloat16, p_kph, g_kph) SYM(__nv_bfloat16, p_kpm, g_kpm) SYM(__nv_bfloat16, p_kpl, g_kpl)
    SYM(__nv_bfloat16, p_cxh, g_cxh) SYM(__nv_bfloat16, p_cxl, g_cxl)
    SYM(__nv_bfloat16, pw_vwh, w_vwh) SYM(__nv_bfloat16, pw_vwl, w_vwl)
    SYM(__nv_bfloat16, pw_qh, w_qh)   SYM(__nv_bfloat16, pw_qm, w_qm)   SYM(__nv_bfloat16, pw_ql, w_ql)
    SYM(__nv_bfloat16, pw_kh, w_kh)   SYM(__nv_bfloat16, pw_km, w_km)   SYM(__nv_bfloat16, pw_kl, w_kl)
    SYM(__nv_bfloat16, pw_wvh, w_wvh) SYM(__nv_bfloat16, pw_wvl, w_wvl)
    SYM(__nv_bfloat16, pw_owh, w_owh) SYM(__nv_bfloat16, pw_owl, w_owl)
    #undef SYM

    const int SM2 = 256 + 2 * 2 * 2 * 16384;   // 131328 (NS=2, 2 stages)
    const int SM3 = 256 + 2 * 3 * 2 * 16384;   // 196864 (NS=3, 2 stages)
    const int SM3_1 = 256 + 3 * 2 * 16384;     //  98560 (NS=3, 1 stage: scores)
    const int SM_PV = 256 + 2 * (2 * 16384 + 2 * 8192);  // 98560
    cudaFuncSetAttribute(hmma_as<2,3,0>, cudaFuncAttributeMaxDynamicSharedMemorySize, SM2);
    cudaFuncSetAttribute(hmma_as<3,6,0>, cudaFuncAttributeMaxDynamicSharedMemorySize, SM3);
    cudaFuncSetAttribute(hmma_as<3,6,1>, cudaFuncAttributeMaxDynamicSharedMemorySize, SM3);
    cudaFuncSetAttribute(pv_gemm, cudaFuncAttributeMaxDynamicSharedMemorySize, SM_PV);

    // ---- prep ----
    expert_sum_kernel<<<dim3(CB / 256, KEXP, 2), 256>>>(q_ex, k_ex);
    dyn_kernel<<<(BB * NN) / 8, 256>>>(y, dynw, dynb);
    scale_kernel<<<dim3(CB / 256, BB * NN), 256>>>();

    const int WN = CB * CB;
    wsplit_kernel<<<WN / 256, 256>>>(v_w, pw_vwh, pw_vwl, nullptr, WN, 2);
    wsplit_kernel<<<WN / 256, 256>>>(in_w, pw_qh, pw_qm, pw_ql, WN, 3);
    wsplit_kernel<<<WN / 256, 256>>>(in_w + (size_t)WN, pw_kh, pw_km, pw_kl, WN, 3);
    wsplit_kernel<<<WN / 256, 256>>>(in_w + (size_t)2 * WN, pw_wvh, pw_wvl, nullptr, WN, 2);
    wsplit_kernel<<<WN / 256, 256>>>(o_w, pw_owh, pw_owl, nullptr, WN, 2);
    qk_split_kernel<<<(int)((size_t)MROWS * CB / 4 / 256), 256>>>(x);

    // ---- GEMMs ----
    // v = x @ v_w^T + v_b  -> split2
    hmma_as<2,3,0><<<dim3(8, 256), 256, SM2>>>(
        p_xh, p_xl, nullptr, pw_vwh, pw_vwl, nullptr,
        nullptr, p_vh, p_vl, nullptr, CB, CB, CB, CB, v_b, nullptr, 1.f);
    // qp = q @ wq^T + bq   -> split3
    hmma_as<3,6,0><<<dim3(8, 256), 256, SM3>>>(
        p_qh, p_qm, p_ql, pw_qh, pw_qm, pw_ql,
        nullptr, p_qph, p_qpm, p_qpl, CB, CB, CB, CB, in_b, nullptr, 1.f);
    // kp = k @ wk^T + bk   -> split3
    hmma_as<3,6,0><<<dim3(8, 256), 256, SM3>>>(
        p_kh, p_km, p_kl, pw_kh, pw_km, pw_kl,
        nullptr, p_kph, p_kpm, p_kpl, CB, CB, CB, CB, in_b + CB, nullptr, 1.f);
    // vp = v @ wv^T + bv   -> fp32
    hmma_as<2,3,0><<<dim3(8, 256), 256, SM2>>>(
        p_vh, p_vl, nullptr, pw_wvh, pw_wvl, nullptr,
        p_vp, nullptr, nullptr, nullptr, CB, CB, CB, CB, in_b + 2 * CB, nullptr, 1.f);

    // scores = qp_h @ kp_h^T / 8  (batched per head, single chunk)
    hmma_as<3,6,1><<<dim3(2, 2, BTT * HH), 256, SM3_1>>>(
        p_qph, p_qpm, p_qpl, p_kph, p_kpm, p_kpl,
        p_attn, nullptr, nullptr, nullptr, HDD, CB, CB, NN, nullptr, nullptr, 0.125f);
    // softmax
    softmax_kernel<<<(BTT * HH * NN) / 8, 256>>>(p_attn);
    // attn_avg
    attn_avg_kernel<<<(BTT * NN * NN) / 256, 256>>>(p_attn, out2);
    // ctx = attn @ vp_h  -> split2 ctx
    pv_gemm<<<dim3(1, 2, BTT * HH), 256, SM_PV>>>(p_attn, p_vp, p_cxh, p_cxl);

    // h = x + ctx @ out_w^T + out_b -> fp32 out1
    hmma_as<2,3,0><<<dim3(8, 256), 256, SM2>>>(
        p_cxh, p_cxl, nullptr, pw_owh, pw_owl, nullptr,
        out1, nullptr, nullptr, nullptr, CB, CB, CB, CB, o_b, x, 1.f);
    // LayerNorm in-place
    ln_kernel<<<MROWS, 256>>>(out1, gam, bet);
}

// round 6
// speedup vs baseline: 2.6964x; 1.3524x over previous
#include <cuda_runtime.h>
#include <cuda_fp16.h>
#include <math.h>
#include <stddef.h>
#include <stdint.h>

// ---------------- problem constants ----------------
constexpr int BB   = 8;
constexpr int TT   = 16;
constexpr int NN   = 256;
constexpr int CB   = 1024;
constexpr int HH   = 16;
constexpr int HDD  = 64;
constexpr int KEXP = 8;
constexpr int BTT  = BB * TT;          // 128
constexpr int MROWS = BTT * NN;        // 32768
constexpr float EPS = 1e-5f;

// ---------------- device scratch ----------------
__device__ __align__(128) float g_qsum[KEXP * CB];
__device__ __align__(128) float g_ksum[KEXP * CB];
__device__ __align__(128) float g_dyn[BB * NN * KEXP];
__device__ __align__(128) float g_qscale[BB * NN * CB];
__device__ __align__(128) float g_kscale[BB * NN * CB];
__device__ __align__(128) float g_attn[(size_t)BTT * HH * NN * NN];   // 537 MB (scores->softmax only)

#define DECL_H(name) __device__ __align__(128) __half name[(size_t)MROWS * CB];
DECL_H(g_xh)  DECL_H(g_xl)
DECL_H(g_qh)  DECL_H(g_ql)
DECL_H(g_kh)  DECL_H(g_kl)
DECL_H(g_vh)  DECL_H(g_vl)
DECL_H(g_qph) DECL_H(g_qpl)
DECL_H(g_kph) DECL_H(g_kpl)
DECL_H(g_vpth) DECL_H(g_vptl)      // vp TRANSPOSED per bt: [bt][c][n]
DECL_H(g_cxh) DECL_H(g_cxl)

__device__ __align__(128) __half g_ah[(size_t)BTT * HH * NN * NN];    // prob splits
__device__ __align__(128) __half g_al[(size_t)BTT * HH * NN * NN];

#define DECL_W(name) __device__ __align__(128) __half name[(size_t)CB * CB];
DECL_W(w_vwh) DECL_W(w_vwl)
DECL_W(w_wqh) DECL_W(w_wql)
DECL_W(w_wkh) DECL_W(w_wkl)
DECL_W(w_wvh) DECL_W(w_wvl)
DECL_W(w_owh) DECL_W(w_owl)

// ---------------- helpers ----------------
__device__ __forceinline__ uint32_t smem_u32(const void* p) {
    return (uint32_t)__cvta_generic_to_shared(p);
}
__device__ __forceinline__ uint32_t sw128(uint32_t o) { return o ^ ((o >> 3) & 0x70); }
__device__ __forceinline__ float hfr(float a) { return __half2float(__float2half_rn(a)); }
__device__ __forceinline__ void ldsm_x4(uint32_t& r0, uint32_t& r1, uint32_t& r2, uint32_t& r3,
                                        uint32_t addr) {
    asm volatile("ldmatrix.sync.aligned.m8n8.x4.shared.b16 {%0,%1,%2,%3}, [%4];"
                 : "=r"(r0), "=r"(r1), "=r"(r2), "=r"(r3) : "r"(addr));
}
__device__ __forceinline__ void mma16816(float* d, const uint32_t* a, uint32_t b0, uint32_t b1) {
    asm volatile("mma.sync.aligned.m16n8k16.row.col.f32.f16.f16.f32 "
                 "{%0,%1,%2,%3}, {%4,%5,%6,%7}, {%8,%9}, {%0,%1,%2,%3};"
                 : "+f"(d[0]), "+f"(d[1]), "+f"(d[2]), "+f"(d[3])
                 : "r"(a[0]), "r"(a[1]), "r"(a[2]), "r"(a[3]), "r"(b0), "r"(b1));
}
__device__ __forceinline__ void cp16(uint32_t dst, const void* src) {
    asm volatile("cp.async.cg.shared.global [%0], [%1], 16;" :: "r"(dst), "l"(src) : "memory");
}
__device__ __forceinline__ void cp_commit() { asm volatile("cp.async.commit_group;" ::: "memory"); }
template<int N> __device__ __forceinline__ void cp_wait() {
    asm volatile("cp.async.wait_group %0;" :: "n"(N) : "memory");
}

// ---------------- fp16 2-split HMMA GEMM, 3-stage cp.async pipeline ----------------
// C = alpha * (A0+A1) @ (B0+B1)^T via products hh,hl,lh (+bias)(+resid)
// BMODE 0: plain NT. 1: scores batch (A,B = head slices; Cf = attn[z]).
// 2: PV batch (A = prob splits [z], lda=NN; B = vpT head slice, ldb=NN; C offset = head cols).
// TRANSC: write split2 output transposed per-bt ([bt][col][row&255]) — for vpT.
template<int BN, int BMODE, bool TRANSC>
__global__ void __launch_bounds__(256)
hmma_f16(const __half* __restrict__ A0, const __half* __restrict__ A1,
         const __half* __restrict__ B0, const __half* __restrict__ B1,
         float* __restrict__ Cf, __half* __restrict__ Ch, __half* __restrict__ Cl,
         int Kdim, int lda, int ldb, int ldc,
         const float* __restrict__ bias, const float* __restrict__ resid, float alpha)
{
    constexpr int ATILE = 128 * 64 * 2;        // 16 KB
    constexpr int BTILE = BN * 64 * 2;
    constexpr int STAGE = 2 * ATILE + 2 * BTILE;
    constexpr int NTILES = BN / 16;            // n-tiles of 8 cols per warp

    extern __shared__ char dsm[];
    const uint32_t sraw  = smem_u32(dsm);
    const uint32_t sbase = (sraw + 127u) & ~127u;

    const int tid  = threadIdx.x;
    const int wid  = tid >> 5;
    const int lane = tid & 31;
    const int wm   = wid & 3;
    const int wn   = wid >> 2;

    const __half* Ap[2] = {A0, A1};
    const __half* Bp[2] = {B0, B1};

    size_t aoff = 0, boff = 0, coff = 0;
    if (BMODE == 1) {
        int z = blockIdx.z;
        size_t off = (size_t)(z >> 4) * NN * CB + (size_t)(z & 15) * HDD;
        aoff = off; boff = off;
        Cf += (size_t)z * NN * NN;
    } else if (BMODE == 2) {
        int z = blockIdx.z;
        aoff = (size_t)z * NN * NN;
        boff = (size_t)(z >> 4) * CB * NN + (size_t)(z & 15) * HDD * NN;
        coff = (size_t)(z >> 4) * NN * CB + (size_t)(z & 15) * HDD;
    }
    const int bm = blockIdx.y * 128, bn = blockIdx.x * BN;

    auto issue = [&](int s, int kt) {
        uint32_t st = sbase + s * STAGE;
        #pragma unroll
        for (int p = 0; p < 2; p++) {
            const __half* As = Ap[p];
            #pragma unroll
            for (int r = 0; r < 4; r++) {
                int i = tid + r * 256;
                int row = i >> 3, ch = (i & 7) * 16;
                cp16(st + p * ATILE + sw128((uint32_t)(row * 128 + ch)),
                     (const char*)(As + aoff + (size_t)(bm + row) * lda + kt) + ch);
            }
        }
        #pragma unroll
        for (int p = 0; p < 2; p++) {
            const __half* Bs = Bp[p];
            #pragma unroll
            for (int r = 0; r < BN * 8 / 256; r++) {
                int i = tid + r * 256;
                int row = i >> 3, ch = (i & 7) * 16;
                cp16(st + 2 * ATILE + p * BTILE + sw128((uint32_t)(row * 128 + ch)),
                     (const char*)(Bs + boff + (size_t)(bn + row) * ldb + kt) + ch);
            }
        }
        cp_commit();
    };

    float acc[2][NTILES][4];
    #pragma unroll
    for (int mt = 0; mt < 2; mt++)
        #pragma unroll
        for (int nt = 0; nt < NTILES; nt++)
            #pragma unroll
            for (int j = 0; j < 4; j++) acc[mt][nt][j] = 0.f;

    const uint32_t a_roff = (uint32_t)((wm * 32 + (lane & 15)) * 128 + ((lane >> 4) << 4));
    const uint32_t b_roff = (uint32_t)((wn * (BN / 2) + ((lane >> 4) << 3) + (lane & 7)) * 128
                                       + (((lane >> 3) & 1) << 4));
    const int PA3[3] = {0, 0, 1}, PB3[3] = {0, 1, 0};

    auto compute = [&](int s) {
        uint32_t st = sbase + s * STAGE;
        #pragma unroll
        for (int p = 0; p < 3; p++) {
            uint32_t abp = st + PA3[p] * ATILE;
            uint32_t bbp = st + 2 * ATILE + PB3[p] * BTILE;
            #pragma unroll
            for (int ks = 0; ks < 4; ks++) {
                uint32_t a[2][4];
                #pragma unroll
                for (int mt = 0; mt < 2; mt++)
                    ldsm_x4(a[mt][0], a[mt][1], a[mt][2], a[mt][3],
                            abp + sw128(a_roff + mt * 16 * 128 + ks * 32));
                #pragma unroll
                for (int bp = 0; bp < NTILES / 2; bp++) {
                    uint32_t b0, b1, b2, b3;
                    ldsm_x4(b0, b1, b2, b3, bbp + sw128(b_roff + bp * 16 * 128 + ks * 32));
                    #pragma unroll
                    for (int mt = 0; mt < 2; mt++) {
                        mma16816(acc[mt][2 * bp],     a[mt], b0, b1);
                        mma16816(acc[mt][2 * bp + 1], a[mt], b2, b3);
                    }
                }
            }
        }
    };

    const int nch = Kdim / 64;
    issue(0, 0);
    if (nch > 1) issue(1, 64);
    if (nch > 2) issue(2, 128);
    for (int t = 0; t < nch; t++) {
        int rem = nch - 1 - t;
        if (rem >= 2) cp_wait<2>();
        else if (rem == 1) cp_wait<1>();
        else cp_wait<0>();
        __syncthreads();
        compute(t % 3);
        __syncthreads();
        if (t + 3 < nch) issue(t % 3, (t + 3) * 64);
    }

    // ---- epilogue ----
    #pragma unroll
    for (int mt = 0; mt < 2; mt++) {
        int r0 = bm + wm * 32 + mt * 16 + (lane >> 2);
        #pragma unroll
        for (int nt = 0; nt < NTILES; nt++) {
            int col = bn + wn * (BN / 2) + nt * 8 + (lane & 3) * 2;
            #pragma unroll
            for (int rr = 0; rr < 2; rr++) {
                int row = r0 + rr * 8;
                float v0 = acc[mt][nt][2 * rr]     * alpha;
                float v1 = acc[mt][nt][2 * rr + 1] * alpha;
                if (bias)  { v0 += bias[col]; v1 += bias[col + 1]; }
                if (resid) {
                    const float* rp = resid + (size_t)row * ldc + col;
                    v0 += rp[0]; v1 += rp[1];
                }
                if (TRANSC) {
                    // write [bt][col][row&255] split2
                    size_t t0 = ((size_t)(row >> 8)) * CB * NN + (size_t)col * NN + (row & 255);
                    float h0 = hfr(v0), h1 = hfr(v1);
                    Ch[t0]      = __float2half_rn(h0);
                    Ch[t0 + NN] = __float2half_rn(h1);
                    Cl[t0]      = __float2half_rn(v0 - h0);
                    Cl[t0 + NN] = __float2half_rn(v1 - h1);
                } else {
                    size_t base = coff + (size_t)row * ldc + col;
                    if (Cf) *(float2*)(Cf + base) = make_float2(v0, v1);
                    if (Ch) {
                        float h0 = hfr(v0), h1 = hfr(v1);
                        __half2 hh = __floats2half2_rn(h0, h1);
                        __half2 ll = __floats2half2_rn(v0 - h0, v1 - h1);
                        *(__half2*)(Ch + base) = hh;
                        *(__half2*)(Cl + base) = ll;
                    }
                }
            }
        }
    }
}

// ---------------- weight split (fp16 2-way) ----------------
__global__ void wsplit_kernel(const float* __restrict__ w, __half* __restrict__ h,
                              __half* __restrict__ l, int n) {
    int i = blockIdx.x * 256 + threadIdx.x;
    if (i >= n) return;
    float a  = w[i];
    float hh = hfr(a);
    h[i] = __float2half_rn(hh);
    l[i] = __float2half_rn(a - hh);
}

// ---------------- x/q/k splits (fp16 2-way; q,k scale fused) ----------------
__global__ void qk_split_kernel(const float* __restrict__ x) {
    size_t idx = (size_t)blockIdx.x * 256 + threadIdx.x;   // over MROWS*CB/4
    size_t row = idx >> 8;
    int c4 = (int)(idx & 255) * 4;
    int srow = (int)(((row >> 12) << 8) | (row & 255));
    float4 xv = *(const float4*)(x + row * CB + c4);
    float4 qs = *(const float4*)(g_qscale + (size_t)srow * CB + c4);
    float4 ks = *(const float4*)(g_kscale + (size_t)srow * CB + c4);
    size_t base = row * CB + c4;

    float xi[4] = {xv.x, xv.y, xv.z, xv.w};
    float qi[4] = {xv.x * qs.x, xv.y * qs.y, xv.z * qs.z, xv.w * qs.w};
    float ki[4] = {xv.x * ks.x, xv.y * ks.y, xv.z * ks.z, xv.w * ks.w};

    __half xh[4], xl[4], qh[4], ql[4], kh[4], kl[4];
    #pragma unroll
    for (int j = 0; j < 4; j++) {
        float h;
        h = hfr(xi[j]); xh[j] = __float2half_rn(h); xl[j] = __float2half_rn(xi[j] - h);
        h = hfr(qi[j]); qh[j] = __float2half_rn(h); ql[j] = __float2half_rn(qi[j] - h);
        h = hfr(ki[j]); kh[j] = __float2half_rn(h); kl[j] = __float2half_rn(ki[j] - h);
    }
    *(uint2*)(g_xh + base) = *(uint2*)xh;  *(uint2*)(g_xl + base) = *(uint2*)xl;
    *(uint2*)(g_qh + base) = *(uint2*)qh;  *(uint2*)(g_ql + base) = *(uint2*)ql;
    *(uint2*)(g_kh + base) = *(uint2*)kh;  *(uint2*)(g_kl + base) = *(uint2*)kl;
}

// ---------------- expert sums ----------------
__global__ void expert_sum_kernel(const float* __restrict__ qe, const float* __restrict__ ke) {
    int c = blockIdx.x * 256 + threadIdx.x;
    int k = blockIdx.y;
    const float* src = blockIdx.z ? ke : qe;
    float* dst = blockIdx.z ? g_ksum : g_qsum;
    const float* p = src + (size_t)k * CB * CB + c;
    float s = 0.f;
    #pragma unroll 4
    for (int r = 0; r < CB; r++) s += p[(size_t)r * CB];
    dst[k * CB + c] = s;
}

// ---------------- dyn softmax ----------------
__global__ void dyn_kernel(const float* __restrict__ y, const float* __restrict__ dw,
                           const float* __restrict__ db) {
    int row  = blockIdx.x * 8 + (threadIdx.x >> 5);
    int lane = threadIdx.x & 31;
    const float* yr = y + (size_t)row * CB;
    float acc[KEXP];
    #pragma unroll
    for (int j = 0; j < KEXP; j++) acc[j] = 0.f;
    for (int c = lane * 4; c < CB; c += 128) {
        float4 yv = *(const float4*)(yr + c);
        #pragma unroll
        for (int j = 0; j < KEXP; j++) {
            float4 w = *(const float4*)(dw + j * CB + c);
            acc[j] += yv.x * w.x + yv.y * w.y + yv.z * w.z + yv.w * w.w;
        }
    }
    #pragma unroll
    for (int j = 0; j < KEXP; j++)
        #pragma unroll
        for (int off = 16; off > 0; off >>= 1)
            acc[j] += __shfl_xor_sync(0xffffffffu, acc[j], off);
    if (lane == 0) {
        float l[KEXP], m = -1e30f;
        #pragma unroll
        for (int j = 0; j < KEXP; j++) { l[j] = acc[j] + db[j]; m = fmaxf(m, l[j]); }
        float s = 0.f;
        #pragma unroll
        for (int j = 0; j < KEXP; j++) { l[j] = expf(l[j] - m); s += l[j]; }
        float inv = 1.f / s;
        #pragma unroll
        for (int j = 0; j < KEXP; j++) g_dyn[row * KEXP + j] = l[j] * inv;
    }
}

// ---------------- q/k scales ----------------
__global__ void scale_kernel() {
    int c  = blockIdx.x * 256 + threadIdx.x;
    int bn = blockIdx.y;
    const float* d = g_dyn + bn * KEXP;
    float qs = 0.f, ks = 0.f;
    #pragma unroll
    for (int j = 0; j < KEXP; j++) {
        float dj = d[j];
        qs += dj * g_qsum[j * CB + c];
        ks += dj * g_ksum[j * CB + c];
    }
    g_qscale[(size_t)bn * CB + c] = qs;
    g_kscale[(size_t)bn * CB + c] = ks;
}

// ---------------- softmax: fp32 scores -> fp16 prob splits ----------------
__global__ void softmax_kernel(const float* __restrict__ S,
                               __half* __restrict__ AH, __half* __restrict__ AL) {
    int row  = blockIdx.x * 8 + (threadIdx.x >> 5);
    int lane = threadIdx.x & 31;
    const float* p = S + (size_t)row * NN + lane * 8;
    float4 a = ((const float4*)p)[0];
    float4 b = ((const float4*)p)[1];
    float m = fmaxf(fmaxf(fmaxf(a.x, a.y), fmaxf(a.z, a.w)),
                    fmaxf(fmaxf(b.x, b.y), fmaxf(b.z, b.w)));
    #pragma unroll
    for (int off = 16; off > 0; off >>= 1) m = fmaxf(m, __shfl_xor_sync(0xffffffffu, m, off));
    a.x = __expf(a.x - m); a.y = __expf(a.y - m); a.z = __expf(a.z - m); a.w = __expf(a.w - m);
    b.x = __expf(b.x - m); b.y = __expf(b.y - m); b.z = __expf(b.z - m); b.w = __expf(b.w - m);
    float s = a.x + a.y + a.z + a.w + b.x + b.y + b.z + b.w;
    #pragma unroll
    for (int off = 16; off > 0; off >>= 1) s += __shfl_xor_sync(0xffffffffu, s, off);
    float inv = 1.f / s;
    float v[8] = {a.x * inv, a.y * inv, a.z * inv, a.w * inv,
                  b.x * inv, b.y * inv, b.z * inv, b.w * inv};
    __half hh[8], ll[8];
    #pragma unroll
    for (int j = 0; j < 8; j++) {
        float h = hfr(v[j]);
        hh[j] = __float2half_rn(h);
        ll[j] = __float2half_rn(v[j] - h);
    }
    size_t base = (size_t)row * NN + lane * 8;
    *(uint4*)(AH + base) = *(uint4*)hh;
    *(uint4*)(AL + base) = *(uint4*)ll;
}

// ---------------- attn_avg from prob splits ----------------
__global__ void attn_avg_kernel(const __half* __restrict__ AH, const __half* __restrict__ AL,
                                float* __restrict__ out2) {
    size_t idx = (size_t)blockIdx.x * 256 + threadIdx.x;
    size_t bt  = idx >> 16;
    size_t rem = idx & 65535;
    size_t base = bt * ((size_t)HH * NN * NN) + rem;
    float s = 0.f;
    #pragma unroll
    for (int h = 0; h < HH; h++) {
        size_t o = base + (size_t)h * NN * NN;
        s += __half2float(AH[o]) + __half2float(AL[o]);
    }
    out2[idx] = s * (1.f / HH);
}

// ---------------- LayerNorm ----------------
__device__ __forceinline__ float block_sum(float v) {
    __shared__ float sh[8];
    int lane = threadIdx.x & 31, w = threadIdx.x >> 5;
    #pragma unroll
    for (int off = 16; off > 0; off >>= 1) v += __shfl_xor_sync(0xffffffffu, v, off);
    if (lane == 0) sh[w] = v;
    __syncthreads();
    float t = (threadIdx.x < 8) ? sh[threadIdx.x] : 0.f;
    if (w == 0) {
        #pragma unroll
        for (int off = 4; off > 0; off >>= 1) t += __shfl_xor_sync(0xffffffffu, t, off);
        if (lane == 0) sh[0] = t;
    }
    __syncthreads();
    float r = sh[0];
    __syncthreads();
    return r;
}

__global__ void ln_kernel(float* __restrict__ h, const float* __restrict__ gamma,
                          const float* __restrict__ beta) {
    int row = blockIdx.x;
    float* p = h + (size_t)row * CB;
    float4 v = ((float4*)p)[threadIdx.x];
    float mu = block_sum(v.x + v.y + v.z + v.w) * (1.f / CB);
    float d0 = v.x - mu, d1 = v.y - mu, d2 = v.z - mu, d3 = v.w - mu;
    float var = block_sum(d0 * d0 + d1 * d1 + d2 * d2 + d3 * d3) * (1.f / CB);
    float inv = rsqrtf(var + EPS);
    float4 g  = ((const float4*)gamma)[threadIdx.x];
    float4 be = ((const float4*)beta)[threadIdx.x];
    float4 o;
    o.x = d0 * inv * g.x + be.x;
    o.y = d1 * inv * g.y + be.y;
    o.z = d2 * inv * g.z + be.z;
    o.w = d3 * inv * g.w + be.w;
    ((float4*)p)[threadIdx.x] = o;
}

// ---------------- launch ----------------
extern "C" void kernel_launch(void* const* d_in, const int* in_sizes, int n_in,
                              void* d_out, int out_size) {
    const float* x    = (const float*)d_in[0];
    const float* y    = (const float*)d_in[1];
    const float* q_ex = (const float*)d_in[3];
    const float* k_ex = (const float*)d_in[4];
    const float* dynw = (const float*)d_in[5];
    const float* dynb = (const float*)d_in[6];
    const float* v_b  = (const float*)d_in[8];
    const float* v_w  = (const float*)d_in[7];
    const float* in_w = (const float*)d_in[9];
    const float* in_b = (const float*)d_in[10];
    const float* o_w  = (const float*)d_in[11];
    const float* o_b  = (const float*)d_in[12];
    const float* gam  = (const float*)d_in[13];
    const float* bet  = (const float*)d_in[14];

    float* out1 = (float*)d_out;
    float* out2 = out1 + (size_t)MROWS * CB;

    #define SYM(T, v, s) T* v; cudaGetSymbolAddress((void**)&v, s);
    SYM(float, p_attn, g_attn)
    SYM(__half, p_xh, g_xh)   SYM(__half, p_xl, g_xl)
    SYM(__half, p_qh, g_qh)   SYM(__half, p_ql, g_ql)
    SYM(__half, p_kh, g_kh)   SYM(__half, p_kl, g_kl)
    SYM(__half, p_vh, g_vh)   SYM(__half, p_vl, g_vl)
    SYM(__half, p_qph, g_qph) SYM(__half, p_qpl, g_qpl)
    SYM(__half, p_kph, g_kph) SYM(__half, p_kpl, g_kpl)
    SYM(__half, p_vpth, g_vpth) SYM(__half, p_vptl, g_vptl)
    SYM(__half, p_cxh, g_cxh) SYM(__half, p_cxl, g_cxl)
    SYM(__half, p_ah, g_ah)   SYM(__half, p_al, g_al)
    SYM(__half, pw_vwh, w_vwh) SYM(__half, pw_vwl, w_vwl)
    SYM(__half, pw_wqh, w_wqh) SYM(__half, pw_wql, w_wql)
    SYM(__half, pw_wkh, w_wkh) SYM(__half, pw_wkl, w_wkl)
    SYM(__half, pw_wvh, w_wvh) SYM(__half, pw_wvl, w_wvl)
    SYM(__half, pw_owh, w_owh) SYM(__half, pw_owl, w_owl)
    #undef SYM

    // smem: slack + 3 stages
    const int SM128 = 256 + 3 * (2 * 16384 + 2 * 16384);  // 196864
    const int SM64  = 256 + 3 * (2 * 16384 + 2 * 8192);   // 147712
    cudaFuncSetAttribute(hmma_f16<128,0,false>, cudaFuncAttributeMaxDynamicSharedMemorySize, SM128);
    cudaFuncSetAttribute(hmma_f16<128,0,true >, cudaFuncAttributeMaxDynamicSharedMemorySize, SM128);
    cudaFuncSetAttribute(hmma_f16<128,1,false>, cudaFuncAttributeMaxDynamicSharedMemorySize, SM128);
    cudaFuncSetAttribute(hmma_f16<64 ,2,false>, cudaFuncAttributeMaxDynamicSharedMemorySize, SM64);

    // ---- prep ----
    expert_sum_kernel<<<dim3(CB / 256, KEXP, 2), 256>>>(q_ex, k_ex);
    dyn_kernel<<<(BB * NN) / 8, 256>>>(y, dynw, dynb);
    scale_kernel<<<dim3(CB / 256, BB * NN), 256>>>();

    const int WN = CB * CB;
    wsplit_kernel<<<WN / 256, 256>>>(v_w, pw_vwh, pw_vwl, WN);
    wsplit_kernel<<<WN / 256, 256>>>(in_w, pw_wqh, pw_wql, WN);
    wsplit_kernel<<<WN / 256, 256>>>(in_w + (size_t)WN, pw_wkh, pw_wkl, WN);
    wsplit_kernel<<<WN / 256, 256>>>(in_w + (size_t)2 * WN, pw_wvh, pw_wvl, WN);
    wsplit_kernel<<<WN / 256, 256>>>(o_w, pw_owh, pw_owl, WN);
    qk_split_kernel<<<(int)((size_t)MROWS * CB / 4 / 256), 256>>>(x);

    // ---- GEMMs ----
    // v = x @ v_w^T + v_b  -> split2
    hmma_f16<128,0,false><<<dim3(8, 256), 256, SM128>>>(
        p_xh, p_xl, pw_vwh, pw_vwl, nullptr, p_vh, p_vl,
        CB, CB, CB, CB, v_b, nullptr, 1.f);
    // qp = q @ wq^T + bq   -> split2
    hmma_f16<128,0,false><<<dim3(8, 256), 256, SM128>>>(
        p_qh, p_ql, pw_wqh, pw_wql, nullptr, p_qph, p_qpl,
        CB, CB, CB, CB, in_b, nullptr, 1.f);
    // kp = k @ wk^T + bk   -> split2
    hmma_f16<128,0,false><<<dim3(8, 256), 256, SM128>>>(
        p_kh, p_kl, pw_wkh, pw_wkl, nullptr, p_kph, p_kpl,
        CB, CB, CB, CB, in_b + CB, nullptr, 1.f);
    // vp = v @ wv^T + bv   -> TRANSPOSED split2 (vpT)
    hmma_f16<128,0,true><<<dim3(8, 256), 256, SM128>>>(
        p_vh, p_vl, pw_wvh, pw_wvl, nullptr, p_vpth, p_vptl,
        CB, CB, CB, CB, in_b + 2 * CB, nullptr, 1.f);

    // scores = qp_h @ kp_h^T / 8 (batched per head, K=64)
    hmma_f16<128,1,false><<<dim3(2, 2, BTT * HH), 256, SM128>>>(
        p_qph, p_qpl, p_kph, p_kpl, p_attn, nullptr, nullptr,
        HDD, CB, CB, NN, nullptr, nullptr, 0.125f);
    // softmax -> prob splits
    softmax_kernel<<<(BTT * HH * NN) / 8, 256>>>(p_attn, p_ah, p_al);
    // attn_avg
    attn_avg_kernel<<<(BTT * NN * NN) / 256, 256>>>(p_ah, p_al, out2);
    // ctx = probs @ vp_h  (fully async, batched per head, K=256)
    hmma_f16<64,2,false><<<dim3(1, 2, BTT * HH), 256, SM64>>>(
        p_ah, p_al, p_vpth, p_vptl, nullptr, p_cxh, p_cxl,
        NN, NN, NN, CB, nullptr, nullptr, 1.f);

    // h = x + ctx @ out_w^T + out_b -> fp32 out1
    hmma_f16<128,0,false><<<dim3(8, 256), 256, SM128>>>(
        p_cxh, p_cxl, pw_owh, pw_owl, out1, nullptr, nullptr,
        CB, CB, CB, CB, o_b, x, 1.f);
    // LayerNorm in-place
    ln_kernel<<<MROWS, 256>>>(out1, gam, bet);
}

// round 7
// speedup vs baseline: 3.4957x; 1.2964x over previous
#include <cuda_runtime.h>
#include <cuda_fp16.h>
#include <math.h>
#include <stddef.h>
#include <stdint.h>

// ---------------- problem constants ----------------
constexpr int BB   = 8;
constexpr int TT   = 16;
constexpr int NN   = 256;
constexpr int CB   = 1024;
constexpr int HH   = 16;
constexpr int HDD  = 64;
constexpr int KEXP = 8;
constexpr int BTT  = BB * TT;          // 128
constexpr int MROWS = BTT * NN;        // 32768
constexpr float EPS = 1e-5f;

// ---------------- device scratch ----------------
__device__ __align__(128) float g_qsum[KEXP * CB];
__device__ __align__(128) float g_ksum[KEXP * CB];
__device__ __align__(128) float g_dyn[BB * NN * KEXP];
__device__ __align__(128) float g_qscale[BB * NN * CB];
__device__ __align__(128) float g_kscale[BB * NN * CB];
__device__ __align__(128) float g_attn[(size_t)BTT * HH * NN * NN];   // 537 MB (scores->softmax only)

#define DECL_H(name) __device__ __align__(128) __half name[(size_t)MROWS * CB];
DECL_H(g_xh)
DECL_H(g_qh)  DECL_H(g_ql)
DECL_H(g_kh)  DECL_H(g_kl)
DECL_H(g_vh)
DECL_H(g_qph) DECL_H(g_qpl)
DECL_H(g_kph) DECL_H(g_kpl)
DECL_H(g_vpth) DECL_H(g_vptl)      // vp TRANSPOSED per bt: [bt][c][n]
DECL_H(g_cxh) DECL_H(g_cxl)

__device__ __align__(128) __half g_ah[(size_t)BTT * HH * NN * NN];    // prob splits
__device__ __align__(128) __half g_al[(size_t)BTT * HH * NN * NN];

#define DECL_W(name) __device__ __align__(128) __half name[(size_t)CB * CB];
DECL_W(w_vwh)
DECL_W(w_wqh) DECL_W(w_wql)
DECL_W(w_wkh) DECL_W(w_wkl)
DECL_W(w_wvh)
DECL_W(w_owh)

// ---------------- helpers ----------------
__device__ __forceinline__ uint32_t smem_u32(const void* p) {
    return (uint32_t)__cvta_generic_to_shared(p);
}
__device__ __forceinline__ uint32_t sw128(uint32_t o) { return o ^ ((o >> 3) & 0x70); }
__device__ __forceinline__ float hfr(float a) { return __half2float(__float2half_rn(a)); }
__device__ __forceinline__ void ldsm_x4(uint32_t& r0, uint32_t& r1, uint32_t& r2, uint32_t& r3,
                                        uint32_t addr) {
    asm volatile("ldmatrix.sync.aligned.m8n8.x4.shared.b16 {%0,%1,%2,%3}, [%4];"
                 : "=r"(r0), "=r"(r1), "=r"(r2), "=r"(r3) : "r"(addr));
}
__device__ __forceinline__ void mma16816(float* d, const uint32_t* a, uint32_t b0, uint32_t b1) {
    asm volatile("mma.sync.aligned.m16n8k16.row.col.f32.f16.f16.f32 "
                 "{%0,%1,%2,%3}, {%4,%5,%6,%7}, {%8,%9}, {%0,%1,%2,%3};"
                 : "+f"(d[0]), "+f"(d[1]), "+f"(d[2]), "+f"(d[3])
                 : "r"(a[0]), "r"(a[1]), "r"(a[2]), "r"(a[3]), "r"(b0), "r"(b1));
}
__device__ __forceinline__ void cp16(uint32_t dst, const void* src) {
    asm volatile("cp.async.cg.shared.global [%0], [%1], 16;" :: "r"(dst), "l"(src) : "memory");
}
__device__ __forceinline__ void cp_commit() { asm volatile("cp.async.commit_group;" ::: "memory"); }
template<int N> __device__ __forceinline__ void cp_wait() {
    asm volatile("cp.async.wait_group %0;" :: "n"(N) : "memory");
}

// ---------------- fp16 split HMMA GEMM, 3-stage cp.async pipeline ----------------
// NPROD=3: (A0+A1)@(B0+B1) via hh,hl,lh.  NPROD=2: A split, B single: hh,lh.
// NPROD=1: single product A0@B0.
// BMODE 0: plain NT. 1: scores batch. 2: PV batch (A=prob splits, B=vpT head slice).
// TRANSC: write split2 output transposed per-bt ([bt][col][row&255]) — for vpT.
template<int BN, int NPROD, int BMODE, bool TRANSC>
__global__ void __launch_bounds__(256, NPROD == 1 ? 2 : 1)
hmma_f16(const __half* __restrict__ A0, const __half* __restrict__ A1,
         const __half* __restrict__ B0, const __half* __restrict__ B1,
         float* __restrict__ Cf, __half* __restrict__ Ch, __half* __restrict__ Cl,
         int Kdim, int lda, int ldb, int ldc,
         const float* __restrict__ bias, const float* __restrict__ resid, float alpha)
{
    constexpr int NSA = (NPROD >= 2) ? 2 : 1;
    constexpr int NSB = (NPROD == 3) ? 2 : 1;
    constexpr int ATILE = 128 * 64 * 2;        // 16 KB
    constexpr int BTILE = BN * 64 * 2;
    constexpr int STAGE = NSA * ATILE + NSB * BTILE;
    constexpr int NTILES = BN / 16;            // n-tiles of 8 cols per warp

    extern __shared__ char dsm[];
    const uint32_t sraw  = smem_u32(dsm);
    const uint32_t sbase = (sraw + 127u) & ~127u;

    const int tid  = threadIdx.x;
    const int wid  = tid >> 5;
    const int lane = tid & 31;
    const int wm   = wid & 3;
    const int wn   = wid >> 2;

    const __half* Ap[2] = {A0, A1};
    const __half* Bp[2] = {B0, B1};

    size_t aoff = 0, boff = 0, coff = 0;
    if (BMODE == 1) {
        int z = blockIdx.z;
        size_t off = (size_t)(z >> 4) * NN * CB + (size_t)(z & 15) * HDD;
        aoff = off; boff = off;
        Cf += (size_t)z * NN * NN;
    } else if (BMODE == 2) {
        int z = blockIdx.z;
        aoff = (size_t)z * NN * NN;
        boff = (size_t)(z >> 4) * CB * NN + (size_t)(z & 15) * HDD * NN;
        coff = (size_t)(z >> 4) * NN * CB + (size_t)(z & 15) * HDD;
    }
    const int bm = blockIdx.y * 128, bn = blockIdx.x * BN;

    auto issue = [&](int s, int kt) {
        uint32_t st = sbase + s * STAGE;
        #pragma unroll
        for (int p = 0; p < NSA; p++) {
            const __half* As = Ap[p];
            #pragma unroll
            for (int r = 0; r < 4; r++) {
                int i = tid + r * 256;
                int row = i >> 3, ch = (i & 7) * 16;
                cp16(st + p * ATILE + sw128((uint32_t)(row * 128 + ch)),
                     (const char*)(As + aoff + (size_t)(bm + row) * lda + kt) + ch);
            }
        }
        #pragma unroll
        for (int p = 0; p < NSB; p++) {
            const __half* Bs = Bp[p];
            #pragma unroll
            for (int r = 0; r < BN * 8 / 256; r++) {
                int i = tid + r * 256;
                int row = i >> 3, ch = (i & 7) * 16;
                cp16(st + NSA * ATILE + p * BTILE + sw128((uint32_t)(row * 128 + ch)),
                     (const char*)(Bs + boff + (size_t)(bn + row) * ldb + kt) + ch);
            }
        }
        cp_commit();
    };

    float acc[2][NTILES][4];
    #pragma unroll
    for (int mt = 0; mt < 2; mt++)
        #pragma unroll
        for (int nt = 0; nt < NTILES; nt++)
            #pragma unroll
            for (int j = 0; j < 4; j++) acc[mt][nt][j] = 0.f;

    const uint32_t a_roff = (uint32_t)((wm * 32 + (lane & 15)) * 128 + ((lane >> 4) << 4));
    const uint32_t b_roff = (uint32_t)((wn * (BN / 2) + ((lane >> 4) << 3) + (lane & 7)) * 128
                                       + (((lane >> 3) & 1) << 4));

    auto compute = [&](int s) {
        uint32_t st = sbase + s * STAGE;
        #pragma unroll
        for (int p = 0; p < NPROD; p++) {
            int pa, pb;
            if (NPROD == 3)      { pa = (p == 2) ? 1 : 0; pb = (p == 1) ? 1 : 0; }
            else if (NPROD == 2) { pa = p; pb = 0; }
            else                 { pa = 0; pb = 0; }
            uint32_t abp = st + pa * ATILE;
            uint32_t bbp = st + NSA * ATILE + pb * BTILE;
            #pragma unroll
            for (int ks = 0; ks < 4; ks++) {
                uint32_t a[2][4];
                #pragma unroll
                for (int mt = 0; mt < 2; mt++)
                    ldsm_x4(a[mt][0], a[mt][1], a[mt][2], a[mt][3],
                            abp + sw128(a_roff + mt * 16 * 128 + ks * 32));
                #pragma unroll
                for (int bp = 0; bp < NTILES / 2; bp++) {
                    uint32_t b0, b1, b2, b3;
                    ldsm_x4(b0, b1, b2, b3, bbp + sw128(b_roff + bp * 16 * 128 + ks * 32));
                    #pragma unroll
                    for (int mt = 0; mt < 2; mt++) {
                        mma16816(acc[mt][2 * bp],     a[mt], b0, b1);
                        mma16816(acc[mt][2 * bp + 1], a[mt], b2, b3);
                    }
                }
            }
        }
    };

    const int nch = Kdim / 64;
    issue(0, 0);
    if (nch > 1) issue(1, 64);
    if (nch > 2) issue(2, 128);
    for (int t = 0; t < nch; t++) {
        int rem = nch - 1 - t;
        if (rem >= 2) cp_wait<2>();
        else if (rem == 1) cp_wait<1>();
        else cp_wait<0>();
        __syncthreads();
        compute(t % 3);
        __syncthreads();
        if (t + 3 < nch) issue(t % 3, (t + 3) * 64);
    }

    // ---- epilogue ----
    #pragma unroll
    for (int mt = 0; mt < 2; mt++) {
        int r0 = bm + wm * 32 + mt * 16 + (lane >> 2);
        #pragma unroll
        for (int nt = 0; nt < NTILES; nt++) {
            int col = bn + wn * (BN / 2) + nt * 8 + (lane & 3) * 2;
            #pragma unroll
            for (int rr = 0; rr < 2; rr++) {
                int row = r0 + rr * 8;
                float v0 = acc[mt][nt][2 * rr]     * alpha;
                float v1 = acc[mt][nt][2 * rr + 1] * alpha;
                if (bias)  { v0 += bias[col]; v1 += bias[col + 1]; }
                if (resid) {
                    const float* rp = resid + (size_t)row * ldc + col;
                    v0 += rp[0]; v1 += rp[1];
                }
                if (TRANSC) {
                    size_t t0 = ((size_t)(row >> 8)) * CB * NN + (size_t)col * NN + (row & 255);
                    float h0 = hfr(v0), h1 = hfr(v1);
                    Ch[t0]      = __float2half_rn(h0);
                    Ch[t0 + NN] = __float2half_rn(h1);
                    Cl[t0]      = __float2half_rn(v0 - h0);
                    Cl[t0 + NN] = __float2half_rn(v1 - h1);
                } else {
                    size_t base = coff + (size_t)row * ldc + col;
                    if (Cf) *(float2*)(Cf + base) = make_float2(v0, v1);
                    if (Ch && Cl) {
                        float h0 = hfr(v0), h1 = hfr(v1);
                        *(__half2*)(Ch + base) = __floats2half2_rn(h0, h1);
                        *(__half2*)(Cl + base) = __floats2half2_rn(v0 - h0, v1 - h1);
                    } else if (Ch) {
                        *(__half2*)(Ch + base) = __floats2half2_rn(v0, v1);
                    }
                }
            }
        }
    }
}

// ---------------- weight split (fp16 2-way) / round-only ----------------
__global__ void wsplit_kernel(const float* __restrict__ w, __half* __restrict__ h,
                              __half* __restrict__ l, int n) {
    int i = blockIdx.x * 256 + threadIdx.x;
    if (i >= n) return;
    float a  = w[i];
    float hh = hfr(a);
    h[i] = __float2half_rn(hh);
    l[i] = __float2half_rn(a - hh);
}
__global__ void wround_kernel(const float* __restrict__ w, __half* __restrict__ h, int n) {
    int i = blockIdx.x * 256 + threadIdx.x;
    if (i >= n) return;
    h[i] = __float2half_rn(w[i]);
}

// ---------------- x round + q/k splits (scale fused) ----------------
__global__ void qk_split_kernel(const float* __restrict__ x) {
    size_t idx = (size_t)blockIdx.x * 256 + threadIdx.x;   // over MROWS*CB/4
    size_t row = idx >> 8;
    int c4 = (int)(idx & 255) * 4;
    int srow = (int)(((row >> 12) << 8) | (row & 255));
    float4 xv = *(const float4*)(x + row * CB + c4);
    float4 qs = *(const float4*)(g_qscale + (size_t)srow * CB + c4);
    float4 ks = *(const float4*)(g_kscale + (size_t)srow * CB + c4);
    size_t base = row * CB + c4;

    float xi[4] = {xv.x, xv.y, xv.z, xv.w};
    float qi[4] = {xv.x * qs.x, xv.y * qs.y, xv.z * qs.z, xv.w * qs.w};
    float ki[4] = {xv.x * ks.x, xv.y * ks.y, xv.z * ks.z, xv.w * ks.w};

    __half xh[4], qh[4], ql[4], kh[4], kl[4];
    #pragma unroll
    for (int j = 0; j < 4; j++) {
        xh[j] = __float2half_rn(xi[j]);
        float h;
        h = hfr(qi[j]); qh[j] = __float2half_rn(h); ql[j] = __float2half_rn(qi[j] - h);
        h = hfr(ki[j]); kh[j] = __float2half_rn(h); kl[j] = __float2half_rn(ki[j] - h);
    }
    *(uint2*)(g_xh + base) = *(uint2*)xh;
    *(uint2*)(g_qh + base) = *(uint2*)qh;  *(uint2*)(g_ql + base) = *(uint2*)ql;
    *(uint2*)(g_kh + base) = *(uint2*)kh;  *(uint2*)(g_kl + base) = *(uint2*)kl;
}

// ---------------- expert sums ----------------
__global__ void expert_sum_kernel(const float* __restrict__ qe, const float* __restrict__ ke) {
    int c = blockIdx.x * 256 + threadIdx.x;
    int k = blockIdx.y;
    const float* src = blockIdx.z ? ke : qe;
    float* dst = blockIdx.z ? g_ksum : g_qsum;
    const float* p = src + (size_t)k * CB * CB + c;
    float s = 0.f;
    #pragma unroll 4
    for (int r = 0; r < CB; r++) s += p[(size_t)r * CB];
    dst[k * CB + c] = s;
}

// ---------------- dyn softmax ----------------
__global__ void dyn_kernel(const float* __restrict__ y, const float* __restrict__ dw,
                           const float* __restrict__ db) {
    int row  = blockIdx.x * 8 + (threadIdx.x >> 5);
    int lane = threadIdx.x & 31;
    const float* yr = y + (size_t)row * CB;
    float acc[KEXP];
    #pragma unroll
    for (int j = 0; j < KEXP; j++) acc[j] = 0.f;
    for (int c = lane * 4; c < CB; c += 128) {
        float4 yv = *(const float4*)(yr + c);
        #pragma unroll
        for (int j = 0; j < KEXP; j++) {
            float4 w = *(const float4*)(dw + j * CB + c);
            acc[j] += yv.x * w.x + yv.y * w.y + yv.z * w.z + yv.w * w.w;
        }
    }
    #pragma unroll
    for (int j = 0; j < KEXP; j++)
        #pragma unroll
        for (int off = 16; off > 0; off >>= 1)
            acc[j] += __shfl_xor_sync(0xffffffffu, acc[j], off);
    if (lane == 0) {
        float l[KEXP], m = -1e30f;
        #pragma unroll
        for (int j = 0; j < KEXP; j++) { l[j] = acc[j] + db[j]; m = fmaxf(m, l[j]); }
        float s = 0.f;
        #pragma unroll
        for (int j = 0; j < KEXP; j++) { l[j] = expf(l[j] - m); s += l[j]; }
        float inv = 1.f / s;
        #pragma unroll
        for (int j = 0; j < KEXP; j++) g_dyn[row * KEXP + j] = l[j] * inv;
    }
}

// ---------------- q/k scales ----------------
__global__ void scale_kernel() {
    int c  = blockIdx.x * 256 + threadIdx.x;
    int bn = blockIdx.y;
    const float* d = g_dyn + bn * KEXP;
    float qs = 0.f, ks = 0.f;
    #pragma unroll
    for (int j = 0; j < KEXP; j++) {
        float dj = d[j];
        qs += dj * g_qsum[j * CB + c];
        ks += dj * g_ksum[j * CB + c];
    }
    g_qscale[(size_t)bn * CB + c] = qs;
    g_kscale[(size_t)bn * CB + c] = ks;
}

// ---------------- softmax: fp32 scores -> fp16 prob splits ----------------
__global__ void softmax_kernel(const float* __restrict__ S,
                               __half* __restrict__ AH, __half* __restrict__ AL) {
    int row  = blockIdx.x * 8 + (threadIdx.x >> 5);
    int lane = threadIdx.x & 31;
    const float* p = S + (size_t)row * NN + lane * 8;
    float4 a = ((const float4*)p)[0];
    float4 b = ((const float4*)p)[1];
    float m = fmaxf(fmaxf(fmaxf(a.x, a.y), fmaxf(a.z, a.w)),
                    fmaxf(fmaxf(b.x, b.y), fmaxf(b.z, b.w)));
    #pragma unroll
    for (int off = 16; off > 0; off >>= 1) m = fmaxf(m, __shfl_xor_sync(0xffffffffu, m, off));
    a.x = __expf(a.x - m); a.y = __expf(a.y - m); a.z = __expf(a.z - m); a.w = __expf(a.w - m);
    b.x = __expf(b.x - m); b.y = __expf(b.y - m); b.z = __expf(b.z - m); b.w = __expf(b.w - m);
    float s = a.x + a.y + a.z + a.w + b.x + b.y + b.z + b.w;
    #pragma unroll
    for (int off = 16; off > 0; off >>= 1) s += __shfl_xor_sync(0xffffffffu, s, off);
    float inv = 1.f / s;
    float v[8] = {a.x * inv, a.y * inv, a.z * inv, a.w * inv,
                  b.x * inv, b.y * inv, b.z * inv, b.w * inv};
    __half hh[8], ll[8];
    #pragma unroll
    for (int j = 0; j < 8; j++) {
        float h = hfr(v[j]);
        hh[j] = __float2half_rn(h);
        ll[j] = __float2half_rn(v[j] - h);
    }
    size_t base = (size_t)row * NN + lane * 8;
    *(uint4*)(AH + base) = *(uint4*)hh;
    *(uint4*)(AL + base) = *(uint4*)ll;
}

// ---------------- attn_avg from prob-high split ----------------
__global__ void attn_avg_kernel(const __half* __restrict__ AH, float* __restrict__ out2) {
    size_t idx = (size_t)blockIdx.x * 256 + threadIdx.x;
    size_t bt  = idx >> 16;
    size_t rem = idx & 65535;
    size_t base = bt * ((size_t)HH * NN * NN) + rem;
    float s = 0.f;
    #pragma unroll
    for (int h = 0; h < HH; h++) s += __half2float(AH[base + (size_t)h * NN * NN]);
    out2[idx] = s * (1.f / HH);
}

// ---------------- LayerNorm ----------------
__device__ __forceinline__ float block_sum(float v) {
    __shared__ float sh[8];
    int lane = threadIdx.x & 31, w = threadIdx.x >> 5;
    #pragma unroll
    for (int off = 16; off > 0; off >>= 1) v += __shfl_xor_sync(0xffffffffu, v, off);
    if (lane == 0) sh[w] = v;
    __syncthreads();
    float t = (threadIdx.x < 8) ? sh[threadIdx.x] : 0.f;
    if (w == 0) {
        #pragma unroll
        for (int off = 4; off > 0; off >>= 1) t += __shfl_xor_sync(0xffffffffu, t, off);
        if (lane == 0) sh[0] = t;
    }
    __syncthreads();
    float r = sh[0];
    __syncthreads();
    return r;
}

__global__ void ln_kernel(float* __restrict__ h, const float* __restrict__ gamma,
                          const float* __restrict__ beta) {
    int row = blockIdx.x;
    float* p = h + (size_t)row * CB;
    float4 v = ((float4*)p)[threadIdx.x];
    float mu = block_sum(v.x + v.y + v.z + v.w) * (1.f / CB);
    float d0 = v.x - mu, d1 = v.y - mu, d2 = v.z - mu, d3 = v.w - mu;
    float var = block_sum(d0 * d0 + d1 * d1 + d2 * d2 + d3 * d3) * (1.f / CB);
    float inv = rsqrtf(var + EPS);
    float4 g  = ((const float4*)gamma)[threadIdx.x];
    float4 be = ((const float4*)beta)[threadIdx.x];
    float4 o;
    o.x = d0 * inv * g.x + be.x;
    o.y = d1 * inv * g.y + be.y;
    o.z = d2 * inv * g.z + be.z;
    o.w = d3 * inv * g.w + be.w;
    ((float4*)p)[threadIdx.x] = o;
}

// ---------------- launch ----------------
extern "C" void kernel_launch(void* const* d_in, const int* in_sizes, int n_in,
                              void* d_out, int out_size) {
    const float* x    = (const float*)d_in[0];
    const float* y    = (const float*)d_in[1];
    const float* q_ex = (const float*)d_in[3];
    const float* k_ex = (const float*)d_in[4];
    const float* dynw = (const float*)d_in[5];
    const float* dynb = (const float*)d_in[6];
    const float* v_w  = (const float*)d_in[7];
    const float* v_b  = (const float*)d_in[8];
    const float* in_w = (const float*)d_in[9];
    const float* in_b = (const float*)d_in[10];
    const float* o_w  = (const float*)d_in[11];
    const float* o_b  = (const float*)d_in[12];
    const float* gam  = (const float*)d_in[13];
    const float* bet  = (const float*)d_in[14];

    float* out1 = (float*)d_out;
    float* out2 = out1 + (size_t)MROWS * CB;

    #define SYM(T, v, s) T* v; cudaGetSymbolAddress((void**)&v, s);
    SYM(float, p_attn, g_attn)
    SYM(__half, p_xh, g_xh)
    SYM(__half, p_qh, g_qh)   SYM(__half, p_ql, g_ql)
    SYM(__half, p_kh, g_kh)   SYM(__half, p_kl, g_kl)
    SYM(__half, p_vh, g_vh)
    SYM(__half, p_qph, g_qph) SYM(__half, p_qpl, g_qpl)
    SYM(__half, p_kph, g_kph) SYM(__half, p_kpl, g_kpl)
    SYM(__half, p_vpth, g_vpth) SYM(__half, p_vptl, g_vptl)
    SYM(__half, p_cxh, g_cxh) SYM(__half, p_cxl, g_cxl)
    SYM(__half, p_ah, g_ah)   SYM(__half, p_al, g_al)
    SYM(__half, pw_vwh, w_vwh)
    SYM(__half, pw_wqh, w_wqh) SYM(__half, pw_wql, w_wql)
    SYM(__half, pw_wkh, w_wkh) SYM(__half, pw_wkl, w_wkl)
    SYM(__half, pw_wvh, w_wvh)
    SYM(__half, pw_owh, w_owh)
    #undef SYM

    // smem: slack + 3 stages
    const int SM_NP3 = 256 + 3 * (2 * 16384 + 2 * 16384);  // 196864
    const int SM_NP2 = 256 + 3 * (2 * 16384 + 16384);      // 147712
    const int SM_NP1 = 256 + 3 * (16384 + 16384);          //  98560
    const int SM_PV  = 256 + 3 * (2 * 16384 + 2 * 8192);   // 147712
    cudaFuncSetAttribute(hmma_f16<128,1,0,false>, cudaFuncAttributeMaxDynamicSharedMemorySize, SM_NP1);
    cudaFuncSetAttribute(hmma_f16<128,1,0,true >, cudaFuncAttributeMaxDynamicSharedMemorySize, SM_NP1);
    cudaFuncSetAttribute(hmma_f16<128,2,0,false>, cudaFuncAttributeMaxDynamicSharedMemorySize, SM_NP2);
    cudaFuncSetAttribute(hmma_f16<128,3,0,false>, cudaFuncAttributeMaxDynamicSharedMemorySize, SM_NP3);
    cudaFuncSetAttribute(hmma_f16<128,3,1,false>, cudaFuncAttributeMaxDynamicSharedMemorySize, SM_NP3);
    cudaFuncSetAttribute(hmma_f16<64 ,3,2,false>, cudaFuncAttributeMaxDynamicSharedMemorySize, SM_PV);

    // ---- prep ----
    expert_sum_kernel<<<dim3(CB / 256, KEXP, 2), 256>>>(q_ex, k_ex);
    dyn_kernel<<<(BB * NN) / 8, 256>>>(y, dynw, dynb);
    scale_kernel<<<dim3(CB / 256, BB * NN), 256>>>();

    const int WN = CB * CB;
    wround_kernel<<<WN / 256, 256>>>(v_w, pw_vwh, WN);
    wsplit_kernel<<<WN / 256, 256>>>(in_w, pw_wqh, pw_wql, WN);
    wsplit_kernel<<<WN / 256, 256>>>(in_w + (size_t)WN, pw_wkh, pw_wkl, WN);
    wround_kernel<<<WN / 256, 256>>>(in_w + (size_t)2 * WN, pw_wvh, WN);
    wround_kernel<<<WN / 256, 256>>>(o_w, pw_owh, WN);
    qk_split_kernel<<<(int)((size_t)MROWS * CB / 4 / 256), 256>>>(x);

    // ---- GEMMs ----
    // v = x @ v_w^T + v_b   (NP1) -> fp16 rounded
    hmma_f16<128,1,0,false><<<dim3(8, 256), 256, SM_NP1>>>(
        p_xh, nullptr, pw_vwh, nullptr, nullptr, p_vh, nullptr,
        CB, CB, CB, CB, v_b, nullptr, 1.f);
    // qp = q @ wq^T + bq    (NP3) -> split2
    hmma_f16<128,3,0,false><<<dim3(8, 256), 256, SM_NP3>>>(
        p_qh, p_ql, pw_wqh, pw_wql, nullptr, p_qph, p_qpl,
        CB, CB, CB, CB, in_b, nullptr, 1.f);
    // kp = k @ wk^T + bk    (NP3) -> split2
    hmma_f16<128,3,0,false><<<dim3(8, 256), 256, SM_NP3>>>(
        p_kh, p_kl, pw_wkh, pw_wkl, nullptr, p_kph, p_kpl,
        CB, CB, CB, CB, in_b + CB, nullptr, 1.f);
    // vp = v @ wv^T + bv    (NP1) -> TRANSPOSED split2 (vpT)
    hmma_f16<128,1,0,true><<<dim3(8, 256), 256, SM_NP1>>>(
        p_vh, nullptr, pw_wvh, nullptr, nullptr, p_vpth, p_vptl,
        CB, CB, CB, CB, in_b + 2 * CB, nullptr, 1.f);

    // scores = qp_h @ kp_h^T / 8 (NP3, batched per head, K=64)
    hmma_f16<128,3,1,false><<<dim3(2, 2, BTT * HH), 256, SM_NP3>>>(
        p_qph, p_qpl, p_kph, p_kpl, p_attn, nullptr, nullptr,
        HDD, CB, CB, NN, nullptr, nullptr, 0.125f);
    // softmax -> prob splits
    softmax_kernel<<<(BTT * HH * NN) / 8, 256>>>(p_attn, p_ah, p_al);
    // attn_avg (high split only)
    attn_avg_kernel<<<(BTT * NN * NN) / 256, 256>>>(p_ah, out2);
    // ctx = probs @ vp_h (NP3, batched per head, K=256)
    hmma_f16<64,3,2,false><<<dim3(1, 2, BTT * HH), 256, SM_PV>>>(
        p_ah, p_al, p_vpth, p_vptl, nullptr, p_cxh, p_cxl,
        NN, NN, NN, CB, nullptr, nullptr, 1.f);

    // h = x + ctx @ out_w^T + out_b (NP2: ctx split2 x weight-hi) -> fp32 out1
    hmma_f16<128,2,0,false><<<dim3(8, 256), 256, SM_NP2>>>(
        p_cxh, p_cxl, pw_owh, nullptr, out1, nullptr, nullptr,
        CB, CB, CB, CB, o_b, x, 1.f);
    // LayerNorm in-place
    ln_kernel<<<MROWS, 256>>>(out1, gam, bet);
}

// round 8
// speedup vs baseline: 3.8801x; 1.1099x over previous
#include <cuda_runtime.h>
#include <cuda_fp16.h>
#include <math.h>
#include <stddef.h>
#include <stdint.h>

// ---------------- problem constants ----------------
constexpr int BB   = 8;
constexpr int TT   = 16;
constexpr int NN   = 256;
constexpr int CB   = 1024;
constexpr int HH   = 16;
constexpr int HDD  = 64;
constexpr int KEXP = 8;
constexpr int BTT  = BB * TT;          // 128
constexpr int MROWS = BTT * NN;        // 32768
constexpr float EPS = 1e-5f;

// ---------------- device scratch ----------------
__device__ __align__(128) float g_qsum[KEXP * CB];
__device__ __align__(128) float g_ksum[KEXP * CB];
__device__ __align__(128) float g_dyn[BB * NN * KEXP];
__device__ __align__(128) float g_qscale[BB * NN * CB];
__device__ __align__(128) float g_kscale[BB * NN * CB];
__device__ __align__(128) float g_bc[CB];

#define DECL_H(name) __device__ __align__(128) __half name[(size_t)MROWS * CB];
DECL_H(g_xh)
DECL_H(g_qh)  DECL_H(g_ql)
DECL_H(g_kh)  DECL_H(g_kl)
DECL_H(g_qph) DECL_H(g_qpl)
DECL_H(g_kph) DECL_H(g_kpl)
DECL_H(g_vpth)                      // vp TRANSPOSED per bt: [bt][d][key]
DECL_H(g_cxh) DECL_H(g_cxl)

__device__ __align__(128) __half g_ah[(size_t)BTT * HH * NN * NN];   // probs fp16

#define DECL_W(name) __device__ __align__(128) __half name[(size_t)CB * CB];
DECL_W(w_wqh) DECL_W(w_wql)
DECL_W(w_wkh) DECL_W(w_wkl)
DECL_W(w_wvh) DECL_W(w_wvl)
DECL_W(w_vwth) DECL_W(w_vwtl)       // vw transposed splits
DECL_W(w_wch) DECL_W(w_wcl)         // Wc = wv @ vw splits
DECL_W(w_owh)

// ---------------- helpers ----------------
__device__ __forceinline__ uint32_t smem_u32(const void* p) {
    return (uint32_t)__cvta_generic_to_shared(p);
}
__device__ __forceinline__ uint32_t sw128(uint32_t o) { return o ^ ((o >> 3) & 0x70); }
__device__ __forceinline__ float hfr(float a) { return __half2float(__float2half_rn(a)); }
__device__ __forceinline__ uint32_t packh2(float a, float b) {
    __half2 t = __floats2half2_rn(a, b);
    return *(uint32_t*)&t;
}
__device__ __forceinline__ void ldsm_x4(uint32_t& r0, uint32_t& r1, uint32_t& r2, uint32_t& r3,
                                        uint32_t addr) {
    asm volatile("ldmatrix.sync.aligned.m8n8.x4.shared.b16 {%0,%1,%2,%3}, [%4];"
                 : "=r"(r0), "=r"(r1), "=r"(r2), "=r"(r3) : "r"(addr));
}
__device__ __forceinline__ void mma16816(float* d, const uint32_t* a, uint32_t b0, uint32_t b1) {
    asm volatile("mma.sync.aligned.m16n8k16.row.col.f32.f16.f16.f32 "
                 "{%0,%1,%2,%3}, {%4,%5,%6,%7}, {%8,%9}, {%0,%1,%2,%3};"
                 : "+f"(d[0]), "+f"(d[1]), "+f"(d[2]), "+f"(d[3])
                 : "r"(a[0]), "r"(a[1]), "r"(a[2]), "r"(a[3]), "r"(b0), "r"(b1));
}
__device__ __forceinline__ void cp16(uint32_t dst, const void* src) {
    asm volatile("cp.async.cg.shared.global [%0], [%1], 16;" :: "r"(dst), "l"(src) : "memory");
}
__device__ __forceinline__ void cp_commit() { asm volatile("cp.async.commit_group;" ::: "memory"); }
template<int N> __device__ __forceinline__ void cp_wait() {
    asm volatile("cp.async.wait_group %0;" :: "n"(N) : "memory");
}

// ---------------- fp16 split HMMA GEMM (plain NT), 3-stage cp.async pipeline ----------------
// NPROD=3: (A0+A1)@(B0+B1) via hh,hl,lh.  NPROD=2: (A0+A1)@B0 via hh,lh.
// OMODE 0: normal row-major out (Cf fp32 and/or Ch/Cl split2), bias per COL, optional resid.
// OMODE 2: vpT write — out[col>>8][row][col&255] half (Ch only), bias per ROW.
template<int NPROD, int OMODE>
__global__ void __launch_bounds__(256)
hmma_f16(const __half* __restrict__ A0, const __half* __restrict__ A1,
         const __half* __restrict__ B0, const __half* __restrict__ B1,
         float* __restrict__ Cf, __half* __restrict__ Ch, __half* __restrict__ Cl,
         int Kdim, int lda, int ldb, int ldc,
         const float* __restrict__ bias, const float* __restrict__ resid)
{
    constexpr int NSA = 2;
    constexpr int NSB = (NPROD == 3) ? 2 : 1;
    constexpr int ATILE = 128 * 64 * 2;        // 16 KB
    constexpr int BTILE = 128 * 64 * 2;
    constexpr int STAGE = NSA * ATILE + NSB * BTILE;

    extern __shared__ char dsm[];
    const uint32_t sraw  = smem_u32(dsm);
    const uint32_t sbase = (sraw + 127u) & ~127u;

    const int tid  = threadIdx.x;
    const int wid  = tid >> 5;
    const int lane = tid & 31;
    const int wm   = wid & 3;
    const int wn   = wid >> 2;

    const __half* Ap[2] = {A0, A1};
    const __half* Bp[2] = {B0, B1};
    const int bm = blockIdx.y * 128, bn = blockIdx.x * 128;

    auto issue = [&](int s, int kt) {
        uint32_t st = sbase + s * STAGE;
        #pragma unroll
        for (int p = 0; p < NSA; p++) {
            const __half* As = Ap[p];
            #pragma unroll
            for (int r = 0; r < 4; r++) {
                int i = tid + r * 256;
                int row = i >> 3, ch = (i & 7) * 16;
                cp16(st + p * ATILE + sw128((uint32_t)(row * 128 + ch)),
                     (const char*)(As + (size_t)(bm + row) * lda + kt) + ch);
            }
        }
        #pragma unroll
        for (int p = 0; p < NSB; p++) {
            const __half* Bs = Bp[p];
            #pragma unroll
            for (int r = 0; r < 4; r++) {
                int i = tid + r * 256;
                int row = i >> 3, ch = (i & 7) * 16;
                cp16(st + NSA * ATILE + p * BTILE + sw128((uint32_t)(row * 128 + ch)),
                     (const char*)(Bs + (size_t)(bn + row) * ldb + kt) + ch);
            }
        }
        cp_commit();
    };

    float acc[2][8][4];
    #pragma unroll
    for (int mt = 0; mt < 2; mt++)
        #pragma unroll
        for (int nt = 0; nt < 8; nt++)
            #pragma unroll
            for (int j = 0; j < 4; j++) acc[mt][nt][j] = 0.f;

    const uint32_t a_roff = (uint32_t)((wm * 32 + (lane & 15)) * 128 + ((lane >> 4) << 4));
    const uint32_t b_roff = (uint32_t)((wn * 64 + ((lane >> 4) << 3) + (lane & 7)) * 128
                                       + (((lane >> 3) & 1) << 4));

    auto compute = [&](int s) {
        uint32_t st = sbase + s * STAGE;
        #pragma unroll
        for (int p = 0; p < NPROD; p++) {
            int pa, pb;
            if (NPROD == 3) { pa = (p == 2) ? 1 : 0; pb = (p == 1) ? 1 : 0; }
            else            { pa = p; pb = 0; }
            uint32_t abp = st + pa * ATILE;
            uint32_t bbp = st + NSA * ATILE + pb * BTILE;
            #pragma unroll
            for (int ks = 0; ks < 4; ks++) {
                uint32_t a[2][4];
                #pragma unroll
                for (int mt = 0; mt < 2; mt++)
                    ldsm_x4(a[mt][0], a[mt][1], a[mt][2], a[mt][3],
                            abp + sw128(a_roff + mt * 16 * 128 + ks * 32));
                #pragma unroll
                for (int bp = 0; bp < 4; bp++) {
                    uint32_t b0, b1, b2, b3;
                    ldsm_x4(b0, b1, b2, b3, bbp + sw128(b_roff + bp * 16 * 128 + ks * 32));
                    #pragma unroll
                    for (int mt = 0; mt < 2; mt++) {
                        mma16816(acc[mt][2 * bp],     a[mt], b0, b1);
                        mma16816(acc[mt][2 * bp + 1], a[mt], b2, b3);
                    }
                }
            }
        }
    };

    const int nch = Kdim / 64;
    issue(0, 0);
    if (nch > 1) issue(1, 64);
    if (nch > 2) issue(2, 128);
    for (int t = 0; t < nch; t++) {
        int rem = nch - 1 - t;
        if (rem >= 2) cp_wait<2>();
        else if (rem == 1) cp_wait<1>();
        else cp_wait<0>();
        __syncthreads();
        compute(t % 3);
        __syncthreads();
        if (t + 3 < nch) issue(t % 3, (t + 3) * 64);
    }

    // ---- epilogue ----
    #pragma unroll
    for (int mt = 0; mt < 2; mt++) {
        int r0 = bm + wm * 32 + mt * 16 + (lane >> 2);
        #pragma unroll
        for (int nt = 0; nt < 8; nt++) {
            int col = bn + wn * 64 + nt * 8 + (lane & 3) * 2;
            #pragma unroll
            for (int rr = 0; rr < 2; rr++) {
                int row = r0 + rr * 8;
                float v0 = acc[mt][nt][2 * rr];
                float v1 = acc[mt][nt][2 * rr + 1];
                if (OMODE == 2) {
                    float b = bias[row];
                    v0 += b; v1 += b;
                    size_t t0 = (size_t)(col >> 8) * (CB * NN) + (size_t)row * NN + (col & 255);
                    *(__half2*)(Ch + t0) = __floats2half2_rn(v0, v1);
                } else {
                    if (bias)  { v0 += bias[col]; v1 += bias[col + 1]; }
                    if (resid) {
                        const float* rp = resid + (size_t)row * ldc + col;
                        v0 += rp[0]; v1 += rp[1];
                    }
                    size_t base = (size_t)row * ldc + col;
                    if (Cf) *(float2*)(Cf + base) = make_float2(v0, v1);
                    if (Ch) {
                        float h0 = hfr(v0), h1 = hfr(v1);
                        *(__half2*)(Ch + base) = __floats2half2_rn(h0, h1);
                        *(__half2*)(Cl + base) = __floats2half2_rn(v0 - h0, v1 - h1);
                    }
                }
            }
        }
    }
}

// ---------------- flash attention: scores + softmax + PV fused ----------------
// grid (2 m-blocks, BT*H). Per block: 128 q-rows x 256 keys x 64 hd.
__global__ void __launch_bounds__(256)
flash_kernel(const __half* __restrict__ qph, const __half* __restrict__ qpl,
             const __half* __restrict__ kph, const __half* __restrict__ kpl,
             const __half* __restrict__ vpt,
             __half* __restrict__ AH, __half* __restrict__ cxh, __half* __restrict__ cxl)
{
    // smem: [0,32K) qp splits | [32K,96K) kp splits | [96K,128K) vh 4 chunks
    // reuse [0,..) after scores: red[256] f32, then sred 128x66 f32
    extern __shared__ char dsm[];
    const uint32_t sraw = smem_u32(dsm);
    const uint32_t sb   = (sraw + 127u) & ~127u;
    char* const ab      = dsm + (sb - sraw);

    const int tid = threadIdx.x, wid = tid >> 5, lane = tid & 31;
    const int wm = wid & 3, wn = wid >> 2;
    const int z = blockIdx.y;
    const int bt = z >> 4, head = z & 15;
    const int bm = blockIdx.x * 128;

    const size_t qoff = (size_t)bt * NN * CB + (size_t)head * HDD;
    const size_t voff = (size_t)bt * CB * NN + (size_t)head * HDD * NN;

    // ---- load everything (one phase) ----
    {
        // qp splits: 128 rows x 128B each
        const __half* qs[2] = {qph, qpl};
        #pragma unroll
        for (int p = 0; p < 2; p++)
            #pragma unroll
            for (int r = 0; r < 4; r++) {
                int i = tid + r * 256;
                int row = i >> 3, ch = (i & 7) * 16;
                cp16(sb + p * 16384 + sw128((uint32_t)(row * 128 + ch)),
                     (const char*)(qs[p] + qoff + (size_t)(bm + row) * CB) + ch);
            }
        // kp splits: 256 rows
        const __half* ks[2] = {kph, kpl};
        #pragma unroll
        for (int p = 0; p < 2; p++)
            #pragma unroll
            for (int r = 0; r < 8; r++) {
                int i = tid + r * 256;
                int row = i >> 3, ch = (i & 7) * 16;
                cp16(sb + 32768 + p * 32768 + sw128((uint32_t)(row * 128 + ch)),
                     (const char*)(ks[p] + qoff + (size_t)row * CB) + ch);
            }
        // vh: 4 chunks of 64 d-rows x 64 keys
        #pragma unroll
        for (int c = 0; c < 4; c++)
            #pragma unroll
            for (int r = 0; r < 2; r++) {
                int i = tid + r * 256;
                int row = i >> 3, ch = (i & 7) * 16;
                cp16(sb + 98304 + c * 8192 + sw128((uint32_t)(row * 128 + ch)),
                     (const char*)(vpt + voff + (size_t)row * NN + c * 64) + ch);
            }
        cp_commit();
        cp_wait<0>();
        __syncthreads();
    }

    // ---- scores: S = qp @ kp^T (NP3 on splits), 128 x 256 ----
    float accS[2][16][4];
    #pragma unroll
    for (int mt = 0; mt < 2; mt++)
        #pragma unroll
        for (int nt = 0; nt < 16; nt++)
            #pragma unroll
            for (int j = 0; j < 4; j++) accS[mt][nt][j] = 0.f;

    const uint32_t a_roff = (uint32_t)((wm * 32 + (lane & 15)) * 128 + ((lane >> 4) << 4));
    const uint32_t b_roff = (uint32_t)((wn * 128 + ((lane >> 4) << 3) + (lane & 7)) * 128
                                       + (((lane >> 3) & 1) << 4));
    #pragma unroll
    for (int p = 0; p < 3; p++) {
        uint32_t abp = sb + ((p == 2) ? 16384 : 0);
        uint32_t bbp = sb + 32768 + ((p == 1) ? 32768 : 0);
        #pragma unroll
        for (int ks = 0; ks < 4; ks++) {
            uint32_t a[2][4];
            #pragma unroll
            for (int mt = 0; mt < 2; mt++)
                ldsm_x4(a[mt][0], a[mt][1], a[mt][2], a[mt][3],
                        abp + sw128(a_roff + mt * 16 * 128 + ks * 32));
            #pragma unroll
            for (int bp = 0; bp < 8; bp++) {
                uint32_t b0, b1, b2, b3;
                ldsm_x4(b0, b1, b2, b3, bbp + sw128(b_roff + bp * 16 * 128 + ks * 32));
                #pragma unroll
                for (int mt = 0; mt < 2; mt++) {
                    mma16816(accS[mt][2 * bp],     a[mt], b0, b1);
                    mma16816(accS[mt][2 * bp + 1], a[mt], b2, b3);
                }
            }
        }
    }
    __syncthreads();   // qp/kp smem free now

    // ---- softmax over rows (alpha = 0.125 folded into exp) ----
    float* red = (float*)ab;   // [2][128]
    float rmax[2][2], rsum[2][2];
    #pragma unroll
    for (int mt = 0; mt < 2; mt++)
        #pragma unroll
        for (int rr = 0; rr < 2; rr++) {
            float m = -1e30f;
            #pragma unroll
            for (int nt = 0; nt < 16; nt++)
                m = fmaxf(m, fmaxf(accS[mt][nt][2 * rr], accS[mt][nt][2 * rr + 1]));
            m = fmaxf(m, __shfl_xor_sync(0xffffffffu, m, 1));
            m = fmaxf(m, __shfl_xor_sync(0xffffffffu, m, 2));
            int rowl = wm * 32 + mt * 16 + rr * 8 + (lane >> 2);
            if ((lane & 3) == 0) red[wn * 128 + rowl] = m;
            rmax[mt][rr] = 0.f;  // placeholder
        }
    __syncthreads();
    #pragma unroll
    for (int mt = 0; mt < 2; mt++)
        #pragma unroll
        for (int rr = 0; rr < 2; rr++) {
            int rowl = wm * 32 + mt * 16 + rr * 8 + (lane >> 2);
            rmax[mt][rr] = fmaxf(red[rowl], red[128 + rowl]);
        }
    __syncthreads();
    #pragma unroll
    for (int mt = 0; mt < 2; mt++)
        #pragma unroll
        for (int rr = 0; rr < 2; rr++) {
            float m = rmax[mt][rr], s = 0.f;
            #pragma unroll
            for (int nt = 0; nt < 16; nt++) {
                float e0 = __expf((accS[mt][nt][2 * rr]     - m) * 0.125f);
                float e1 = __expf((accS[mt][nt][2 * rr + 1] - m) * 0.125f);
                accS[mt][nt][2 * rr]     = e0;
                accS[mt][nt][2 * rr + 1] = e1;
                s += e0 + e1;
            }
            s += __shfl_xor_sync(0xffffffffu, s, 1);
            s += __shfl_xor_sync(0xffffffffu, s, 2);
            int rowl = wm * 32 + mt * 16 + rr * 8 + (lane >> 2);
            if ((lane & 3) == 0) red[wn * 128 + rowl] = s;
        }
    __syncthreads();
    #pragma unroll
    for (int mt = 0; mt < 2; mt++)
        #pragma unroll
        for (int rr = 0; rr < 2; rr++) {
            int rowl = wm * 32 + mt * 16 + rr * 8 + (lane >> 2);
            float inv = 1.f / (red[rowl] + red[128 + rowl]);
            #pragma unroll
            for (int nt = 0; nt < 16; nt++) {
                accS[mt][nt][2 * rr]     *= inv;
                accS[mt][nt][2 * rr + 1] *= inv;
            }
            rsum[mt][rr] = inv;   // keep reg alive (unused later)
        }
    (void)rsum;

    // ---- write probs (fp16) for attn_avg ----
    #pragma unroll
    for (int mt = 0; mt < 2; mt++)
        #pragma unroll
        for (int rr = 0; rr < 2; rr++) {
            int rowl = wm * 32 + mt * 16 + rr * 8 + (lane >> 2);
            size_t rbase = (size_t)z * (NN * NN) + (size_t)(bm + rowl) * NN
                         + wn * 128 + (lane & 3) * 2;
            #pragma unroll
            for (int nt = 0; nt < 16; nt++)
                *(__half2*)(AH + rbase + nt * 8) =
                    __floats2half2_rn(accS[mt][nt][2 * rr], accS[mt][nt][2 * rr + 1]);
        }

    // ---- PV: ctx = P @ V  (P split2 in regs, vh in smem) ----
    float accPV[2][8][4];
    #pragma unroll
    for (int mt = 0; mt < 2; mt++)
        #pragma unroll
        for (int nt = 0; nt < 8; nt++)
            #pragma unroll
            for (int j = 0; j < 4; j++) accPV[mt][nt][j] = 0.f;

    const uint32_t pvb_roff = (uint32_t)((((lane >> 4) << 3) + (lane & 7)) * 128
                                         + (((lane >> 3) & 1) << 4));
    #pragma unroll
    for (int g = 0; g < 8; g++) {
        int cglob = wn * 2 + (g >> 2);
        int ksl = g & 3;
        uint32_t bbase = sb + 98304 + cglob * 8192;
        uint32_t aph[2][4], apl[2][4];
        #pragma unroll
        for (int mt = 0; mt < 2; mt++) {
            #pragma unroll
            for (int t2 = 0; t2 < 2; t2++) {
                int tile = 2 * g + t2;
                float p0 = accS[mt][tile][0], p1 = accS[mt][tile][1];
                float p2 = accS[mt][tile][2], p3 = accS[mt][tile][3];
                float h0 = hfr(p0), h1 = hfr(p1), h2 = hfr(p2), h3 = hfr(p3);
                aph[mt][2 * t2]     = packh2(h0, h1);
                aph[mt][2 * t2 + 1] = packh2(h2, h3);
                apl[mt][2 * t2]     = packh2(p0 - h0, p1 - h1);
                apl[mt][2 * t2 + 1] = packh2(p2 - h2, p3 - h3);
            }
        }
        #pragma unroll
        for (int bp = 0; bp < 4; bp++) {
            uint32_t b0, b1, b2, b3;
            ldsm_x4(b0, b1, b2, b3, bbase + sw128(pvb_roff + bp * 16 * 128 + ksl * 32));
            #pragma unroll
            for (int mt = 0; mt < 2; mt++) {
                mma16816(accPV[mt][2 * bp],     aph[mt], b0, b1);
                mma16816(accPV[mt][2 * bp + 1], aph[mt], b2, b3);
                mma16816(accPV[mt][2 * bp],     apl[mt], b0, b1);
                mma16816(accPV[mt][2 * bp + 1], apl[mt], b2, b3);
            }
        }
    }

    // ---- cross-warp (wn) reduction of PV partials via smem, then write ctx splits ----
    __syncthreads();
    float* sred = (float*)ab;   // 128 x 66
    if (wn == 0) {
        #pragma unroll
        for (int mt = 0; mt < 2; mt++)
            #pragma unroll
            for (int rr = 0; rr < 2; rr++) {
                int rowl = wm * 32 + mt * 16 + rr * 8 + (lane >> 2);
                #pragma unroll
                for (int nt = 0; nt < 8; nt++) {
                    int col = nt * 8 + (lane & 3) * 2;
                    *(float2*)(sred + rowl * 66 + col) =
                        make_float2(accPV[mt][nt][2 * rr], accPV[mt][nt][2 * rr + 1]);
                }
            }
    }
    __syncthreads();
    if (wn == 1) {
        #pragma unroll
        for (int mt = 0; mt < 2; mt++)
            #pragma unroll
            for (int rr = 0; rr < 2; rr++) {
                int rowl = wm * 32 + mt * 16 + rr * 8 + (lane >> 2);
                size_t cbase = (size_t)bt * NN * CB + (size_t)(bm + rowl) * CB
                             + (size_t)head * HDD;
                #pragma unroll
                for (int nt = 0; nt < 8; nt++) {
                    int col = nt * 8 + (lane & 3) * 2;
                    float2 o = *(float2*)(sred + rowl * 66 + col);
                    float v0 = accPV[mt][nt][2 * rr]     + o.x;
                    float v1 = accPV[mt][nt][2 * rr + 1] + o.y;
                    float h0 = hfr(v0), h1 = hfr(v1);
                    *(__half2*)(cxh + cbase + col) = __floats2half2_rn(h0, h1);
                    *(__half2*)(cxl + cbase + col) = __floats2half2_rn(v0 - h0, v1 - h1);
                }
            }
    }
}

// ---------------- weight split / round ----------------
__global__ void wsplit_kernel(const float* __restrict__ w, __half* __restrict__ h,
                              __half* __restrict__ l, int n) {
    int i = blockIdx.x * 256 + threadIdx.x;
    if (i >= n) return;
    float a  = w[i];
    float hh = hfr(a);
    h[i] = __float2half_rn(hh);
    l[i] = __float2half_rn(a - hh);
}
__global__ void wround_kernel(const float* __restrict__ w, __half* __restrict__ h, int n) {
    int i = blockIdx.x * 256 + threadIdx.x;
    if (i >= n) return;
    h[i] = __float2half_rn(w[i]);
}

// ---------------- transpose + split (vw -> vwT splits) ----------------
__global__ void tsplit_kernel(const float* __restrict__ w,
                              __half* __restrict__ th, __half* __restrict__ tl) {
    __shared__ float tile[32][33];
    int bx = blockIdx.x * 32, by = blockIdx.y * 32;
    int tx = threadIdx.x & 31, ty = threadIdx.x >> 5;
    #pragma unroll
    for (int i = 0; i < 4; i++)
        tile[ty + i * 8][tx] = w[(size_t)(by + ty + i * 8) * CB + bx + tx];
    __syncthreads();
    #pragma unroll
    for (int i = 0; i < 4; i++) {
        int orow = bx + ty + i * 8;       // k index
        float a = tile[tx][ty + i * 8];
        float h = hfr(a);
        th[(size_t)orow * CB + by + tx] = __float2half_rn(h);
        tl[(size_t)orow * CB + by + tx] = __float2half_rn(a - h);
    }
}

// ---------------- bc = wv @ v_b + bv ----------------
__global__ void bc_kernel(const float* __restrict__ wv, const float* __restrict__ vb,
                          const float* __restrict__ bv, float* __restrict__ bc) {
    int d = blockIdx.x * 8 + (threadIdx.x >> 5);
    int lane = threadIdx.x & 31;
    const float* wr = wv + (size_t)d * CB;
    float s = 0.f;
    for (int k = lane * 4; k < CB; k += 128) {
        float4 w = *(const float4*)(wr + k);
        float4 v = *(const float4*)(vb + k);
        s += w.x * v.x + w.y * v.y + w.z * v.z + w.w * v.w;
    }
    #pragma unroll
    for (int off = 16; off > 0; off >>= 1) s += __shfl_xor_sync(0xffffffffu, s, off);
    if (lane == 0) bc[d] = s + bv[d];
}

// ---------------- x round + q/k splits (scale fused) ----------------
__global__ void qk_split_kernel(const float* __restrict__ x) {
    size_t idx = (size_t)blockIdx.x * 256 + threadIdx.x;
    size_t row = idx >> 8;
    int c4 = (int)(idx & 255) * 4;
    int srow = (int)(((row >> 12) << 8) | (row & 255));
    float4 xv = *(const float4*)(x + row * CB + c4);
    float4 qs = *(const float4*)(g_qscale + (size_t)srow * CB + c4);
    float4 ks = *(const float4*)(g_kscale + (size_t)srow * CB + c4);
    size_t base = row * CB + c4;

    float xi[4] = {xv.x, xv.y, xv.z, xv.w};
    float qi[4] = {xv.x * qs.x, xv.y * qs.y, xv.z * qs.z, xv.w * qs.w};
    float ki[4] = {xv.x * ks.x, xv.y * ks.y, xv.z * ks.z, xv.w * ks.w};

    __half xh[4], qh[4], ql[4], kh[4], kl[4];
    #pragma unroll
    for (int j = 0; j < 4; j++) {
        xh[j] = __float2half_rn(xi[j]);
        float h;
        h = hfr(qi[j]); qh[j] = __float2half_rn(h); ql[j] = __float2half_rn(qi[j] - h);
        h = hfr(ki[j]); kh[j] = __float2half_rn(h); kl[j] = __float2half_rn(ki[j] - h);
    }
    *(uint2*)(g_xh + base) = *(uint2*)xh;
    *(uint2*)(g_qh + base) = *(uint2*)qh;  *(uint2*)(g_ql + base) = *(uint2*)ql;
    *(uint2*)(g_kh + base) = *(uint2*)kh;  *(uint2*)(g_kl + base) = *(uint2*)kl;
}

// ---------------- expert sums ----------------
__global__ void expert_sum_kernel(const float* __restrict__ qe, const float* __restrict__ ke) {
    int c = blockIdx.x * 256 + threadIdx.x;
    int k = blockIdx.y;
    const float* src = blockIdx.z ? ke : qe;
    float* dst = blockIdx.z ? g_ksum : g_qsum;
    const float* p = src + (size_t)k * CB * CB + c;
    float s = 0.f;
    #pragma unroll 4
    for (int r = 0; r < CB; r++) s += p[(size_t)r * CB];
    dst[k * CB + c] = s;
}

// ---------------- dyn softmax ----------------
__global__ void dyn_kernel(const float* __restrict__ y, const float* __restrict__ dw,
                           const float* __restrict__ db) {
    int row  = blockIdx.x * 8 + (threadIdx.x >> 5);
    int lane = threadIdx.x & 31;
    const float* yr = y + (size_t)row * CB;
    float acc[KEXP];
    #pragma unroll
    for (int j = 0; j < KEXP; j++) acc[j] = 0.f;
    for (int c = lane * 4; c < CB; c += 128) {
        float4 yv = *(const float4*)(yr + c);
        #pragma unroll
        for (int j = 0; j < KEXP; j++) {
            float4 w = *(const float4*)(dw + j * CB + c);
            acc[j] += yv.x * w.x + yv.y * w.y + yv.z * w.z + yv.w * w.w;
        }
    }
    #pragma unroll
    for (int j = 0; j < KEXP; j++)
        #pragma unroll
        for (int off = 16; off > 0; off >>= 1)
            acc[j] += __shfl_xor_sync(0xffffffffu, acc[j], off);
    if (lane == 0) {
        float l[KEXP], m = -1e30f;
        #pragma unroll
        for (int j = 0; j < KEXP; j++) { l[j] = acc[j] + db[j]; m = fmaxf(m, l[j]); }
        float s = 0.f;
        #pragma unroll
        for (int j = 0; j < KEXP; j++) { l[j] = expf(l[j] - m); s += l[j]; }
        float inv = 1.f / s;
        #pragma unroll
        for (int j = 0; j < KEXP; j++) g_dyn[row * KEXP + j] = l[j] * inv;
    }
}

// ---------------- q/k scales ----------------
__global__ void scale_kernel() {
    int c  = blockIdx.x * 256 + threadIdx.x;
    int bn = blockIdx.y;
    const float* d = g_dyn + bn * KEXP;
    float qs = 0.f, ks = 0.f;
    #pragma unroll
    for (int j = 0; j < KEXP; j++) {
        float dj = d[j];
        qs += dj * g_qsum[j * CB + c];
        ks += dj * g_ksum[j * CB + c];
    }
    g_qscale[(size_t)bn * CB + c] = qs;
    g_kscale[(size_t)bn * CB + c] = ks;
}

// ---------------- attn_avg from fp16 probs ----------------
__global__ void attn_avg_kernel(const __half* __restrict__ AH, float* __restrict__ out2) {
    size_t idx = (size_t)blockIdx.x * 256 + threadIdx.x;
    size_t bt  = idx >> 16;
    size_t rem = idx & 65535;
    size_t base = bt * ((size_t)HH * NN * NN) + rem;
    float s = 0.f;
    #pragma unroll
    for (int h = 0; h < HH; h++) s += __half2float(AH[base + (size_t)h * NN * NN]);
    out2[idx] = s * (1.f / HH);
}

// ---------------- LayerNorm ----------------
__device__ __forceinline__ float block_sum(float v) {
    __shared__ float sh[8];
    int lane = threadIdx.x & 31, w = threadIdx.x >> 5;
    #pragma unroll
    for (int off = 16; off > 0; off >>= 1) v += __shfl_xor_sync(0xffffffffu, v, off);
    if (lane == 0) sh[w] = v;
    __syncthreads();
    float t = (threadIdx.x < 8) ? sh[threadIdx.x] : 0.f;
    if (w == 0) {
        #pragma unroll
        for (int off = 4; off > 0; off >>= 1) t += __shfl_xor_sync(0xffffffffu, t, off);
        if (lane == 0) sh[0] = t;
    }
    __syncthreads();
    float r = sh[0];
    __syncthreads();
    return r;
}

__global__ void ln_kernel(float* __restrict__ h, const float* __restrict__ gamma,
                          const float* __restrict__ beta) {
    int row = blockIdx.x;
    float* p = h + (size_t)row * CB;
    float4 v = ((float4*)p)[threadIdx.x];
    float mu = block_sum(v.x + v.y + v.z + v.w) * (1.f / CB);
    float d0 = v.x - mu, d1 = v.y - mu, d2 = v.z - mu, d3 = v.w - mu;
    float var = block_sum(d0 * d0 + d1 * d1 + d2 * d2 + d3 * d3) * (1.f / CB);
    float inv = rsqrtf(var + EPS);
    float4 g  = ((const float4*)gamma)[threadIdx.x];
    float4 be = ((const float4*)beta)[threadIdx.x];
    float4 o;
    o.x = d0 * inv * g.x + be.x;
    o.y = d1 * inv * g.y + be.y;
    o.z = d2 * inv * g.z + be.z;
    o.w = d3 * inv * g.w + be.w;
    ((float4*)p)[threadIdx.x] = o;
}

// ---------------- launch ----------------
extern "C" void kernel_launch(void* const* d_in, const int* in_sizes, int n_in,
                              void* d_out, int out_size) {
    const float* x    = (const float*)d_in[0];
    const float* y    = (const float*)d_in[1];
    const float* q_ex = (const float*)d_in[3];
    const float* k_ex = (const float*)d_in[4];
    const float* dynw = (const float*)d_in[5];
    const float* dynb = (const float*)d_in[6];
    const float* v_w  = (const float*)d_in[7];
    const float* v_b  = (const float*)d_in[8];
    const float* in_w = (const float*)d_in[9];
    const float* in_b = (const float*)d_in[10];
    const float* o_w  = (const float*)d_in[11];
    const float* o_b  = (const float*)d_in[12];
    const float* gam  = (const float*)d_in[13];
    const float* bet  = (const float*)d_in[14];

    float* out1 = (float*)d_out;
    float* out2 = out1 + (size_t)MROWS * CB;

    #define SYM(T, v, s) T* v; cudaGetSymbolAddress((void**)&v, s);
    SYM(float, p_bc, g_bc)
    SYM(__half, p_xh, g_xh)
    SYM(__half, p_qh, g_qh)   SYM(__half, p_ql, g_ql)
    SYM(__half, p_kh, g_kh)   SYM(__half, p_kl, g_kl)
    SYM(__half, p_qph, g_qph) SYM(__half, p_qpl, g_qpl)
    SYM(__half, p_kph, g_kph) SYM(__half, p_kpl, g_kpl)
    SYM(__half, p_vpth, g_vpth)
    SYM(__half, p_cxh, g_cxh) SYM(__half, p_cxl, g_cxl)
    SYM(__half, p_ah, g_ah)
    SYM(__half, pw_wqh, w_wqh) SYM(__half, pw_wql, w_wql)
    SYM(__half, pw_wkh, w_wkh) SYM(__half, pw_wkl, w_wkl)
    SYM(__half, pw_wvh, w_wvh) SYM(__half, pw_wvl, w_wvl)
    SYM(__half, pw_vwth, w_vwth) SYM(__half, pw_vwtl, w_vwtl)
    SYM(__half, pw_wch, w_wch) SYM(__half, pw_wcl, w_wcl)
    SYM(__half, pw_owh, w_owh)
    #undef SYM

    const int SM_NP3 = 256 + 3 * (4 * 16384);   // 196864
    const int SM_NP2 = 256 + 3 * (3 * 16384);   // 147712
    const int SM_FL  = 256 + 131072;            // 131328
    cudaFuncSetAttribute(hmma_f16<3,0>, cudaFuncAttributeMaxDynamicSharedMemorySize, SM_NP3);
    cudaFuncSetAttribute(hmma_f16<2,0>, cudaFuncAttributeMaxDynamicSharedMemorySize, SM_NP2);
    cudaFuncSetAttribute(hmma_f16<2,2>, cudaFuncAttributeMaxDynamicSharedMemorySize, SM_NP2);
    cudaFuncSetAttribute(flash_kernel,  cudaFuncAttributeMaxDynamicSharedMemorySize, SM_FL);

    // ---- prep ----
    expert_sum_kernel<<<dim3(CB / 256, KEXP, 2), 256>>>(q_ex, k_ex);
    dyn_kernel<<<(BB * NN) / 8, 256>>>(y, dynw, dynb);
    scale_kernel<<<dim3(CB / 256, BB * NN), 256>>>();

    const int WN = CB * CB;
    wsplit_kernel<<<WN / 256, 256>>>(in_w, pw_wqh, pw_wql, WN);
    wsplit_kernel<<<WN / 256, 256>>>(in_w + (size_t)WN, pw_wkh, pw_wkl, WN);
    wsplit_kernel<<<WN / 256, 256>>>(in_w + (size_t)2 * WN, pw_wvh, pw_wvl, WN);
    wround_kernel<<<WN / 256, 256>>>(o_w, pw_owh, WN);
    tsplit_kernel<<<dim3(32, 32), 256>>>(v_w, pw_vwth, pw_vwtl);
    bc_kernel<<<CB / 8, 256>>>(in_w + (size_t)2 * WN, v_b, in_b + 2 * CB, p_bc);
    qk_split_kernel<<<(int)((size_t)MROWS * CB / 4 / 256), 256>>>(x);

    // ---- Wc = wv @ vw  (split2 output) ----
    hmma_f16<3,0><<<dim3(8, 8), 256, SM_NP3>>>(
        pw_wvh, pw_wvl, pw_vwth, pw_vwtl, nullptr, pw_wch, pw_wcl,
        CB, CB, CB, CB, nullptr, nullptr);

    // ---- vpT = Wc @ x^T + bc  (OMODE2: per-bt transposed half output, row bias) ----
    hmma_f16<2,2><<<dim3(256, 8), 256, SM_NP2>>>(
        pw_wch, pw_wcl, p_xh, nullptr, nullptr, p_vpth, nullptr,
        CB, CB, CB, CB, p_bc, nullptr);

    // ---- qp / kp (NP3, split2 outputs) ----
    hmma_f16<3,0><<<dim3(8, 256), 256, SM_NP3>>>(
        p_qh, p_ql, pw_wqh, pw_wql, nullptr, p_qph, p_qpl,
        CB, CB, CB, CB, in_b, nullptr);
    hmma_f16<3,0><<<dim3(8, 256), 256, SM_NP3>>>(
        p_kh, p_kl, pw_wkh, pw_wkl, nullptr, p_kph, p_kpl,
        CB, CB, CB, CB, in_b + CB, nullptr);

    // ---- flash attention ----
    flash_kernel<<<dim3(2, BTT * HH), 256, SM_FL>>>(
        p_qph, p_qpl, p_kph, p_kpl, p_vpth, p_ah, p_cxh, p_cxl);

    // ---- attn_avg ----
    attn_avg_kernel<<<(BTT * NN * NN) / 256, 256>>>(p_ah, out2);

    // ---- h = x + ctx @ out_w^T + out_b ----
    hmma_f16<2,0><<<dim3(8, 256), 256, SM_NP2>>>(
        p_cxh, p_cxl, pw_owh, nullptr, out1, nullptr, nullptr,
        CB, CB, CB, CB, o_b, x);
    // ---- LayerNorm in-place ----
    ln_kernel<<<MROWS, 256>>>(out1, gam, bet);
}